// round 11
// baseline (speedup 1.0000x reference)
#include <cuda_runtime.h>
#include <cstdint>

// Problem constants
#define Bc    2
#define Nc    128
#define Sc    4
#define DGc   8
#define CINc  4
#define COUTc 8
#define HIDc  32

// Static smem layout (float offsets). ALL weights non-duplicated, input-major
// [c][k][o]; all weights & biases pre-scaled by 0.5 at staging (silu trick).
#define KYW1t 0        // [c][k2][o]   256
#define KGW1t 256      // [c][k8][o]   1024
#define KYB1o 1280     // [c][o]       128
#define KGB1o 1408     // 128
#define KYW2t 1536     // [c][k32][o]  4096
#define KGW2t 5632     // 4096
#define KYB2o 9728     // 128
#define KGB2o 9856     // 128
#define KYW3o 9984     // 128
#define KGW3o 10112    // 128
#define KYB3o 10240    // 4
#define KGB3o 10244    // 4
#define WOUTo 10248    // 32
#define SREDo 10280    // 64
#define SWTOT 10344

typedef unsigned long long u64;

__device__ __forceinline__ u64 pk2(float lo, float hi) {
    u64 r; asm("mov.b64 %0, {%1, %2};" : "=l"(r) : "f"(lo), "f"(hi)); return r;
}
__device__ __forceinline__ void upk2(u64 v, float& lo, float& hi) {
    asm("mov.b64 {%0, %1}, %2;" : "=f"(lo), "=f"(hi) : "l"(v));
}
__device__ __forceinline__ u64 fma2(u64 a, u64 b, u64 c) {
    u64 d; asm("fma.rn.f32x2 %0, %1, %2, %3;" : "=l"(d) : "l"(a), "l"(b), "l"(c)); return d;
}
__device__ __forceinline__ u64 add2(u64 a, u64 b) {
    u64 d; asm("add.rn.f32x2 %0, %1, %2;" : "=l"(d) : "l"(a), "l"(b)); return d;
}
__device__ __forceinline__ float ex2f(float x) {
    float r; asm("ex2.approx.f32 %0, %1;" : "=f"(r) : "f"(x)); return r;
}
__device__ __forceinline__ float tanhf_a(float x) {
    float r; asm("tanh.approx.f32 %0, %1;" : "=f"(r) : "f"(x)); return r;
}

#define LOG2E 1.4426950408889634f

// Pre-scaled silu: acc holds x/2; silu(x) = fma(acc, tanh(acc), acc).
__device__ __forceinline__ u64 silu2p(u64 acc) {
    float a, b; upk2(acc, a, b);
    u64 tp = pk2(tanhf_a(a), tanhf_a(b));
    return fma2(acc, tp, acc);
}
__device__ __forceinline__ float silu_fp(float acc) {
    return fmaf(acc, tanhf_a(acc), acc);
}

// Fused layers 2+3, 4 chunks of 8 outputs (small acc footprint).
__device__ __forceinline__ void mlp23(const u64* hpA, const u64* hpB,
                                      const float* __restrict__ w2,
                                      const float* __restrict__ b2,
                                      const float* __restrict__ w3,
                                      float b3, float& kA, float& kB)
{
    u64 tA = pk2(0.f, 0.f), tB = pk2(0.f, 0.f);

    #pragma unroll 1
    for (int ch = 0; ch < 4; ++ch) {
        u64 aA[4], aB[4];
        {
            ulonglong2 b01 = *reinterpret_cast<const ulonglong2*>(b2 + ch*8);
            ulonglong2 b23 = *reinterpret_cast<const ulonglong2*>(b2 + ch*8 + 4);
            aA[0]=b01.x; aA[1]=b01.y; aA[2]=b23.x; aA[3]=b23.y;
            aB[0]=b01.x; aB[1]=b01.y; aB[2]=b23.x; aB[3]=b23.y;
        }
        const float* wkb = w2 + ch*8;
        #pragma unroll
        for (int p = 0; p < 16; ++p) {
            float ha0, ha1, hb0, hb1;
            upk2(hpA[p], ha0, ha1);
            upk2(hpB[p], hb0, hb1);
            {   // k = 2p
                const u64 hAd = pk2(ha0, ha0);
                const u64 hBd = pk2(hb0, hb0);
                ulonglong2 w01 = *reinterpret_cast<const ulonglong2*>(wkb + (2*p)*32);
                ulonglong2 w23 = *reinterpret_cast<const ulonglong2*>(wkb + (2*p)*32 + 4);
                aA[0] = fma2(hAd, w01.x, aA[0]);
                aA[1] = fma2(hAd, w01.y, aA[1]);
                aA[2] = fma2(hAd, w23.x, aA[2]);
                aA[3] = fma2(hAd, w23.y, aA[3]);
                aB[0] = fma2(hBd, w01.x, aB[0]);
                aB[1] = fma2(hBd, w01.y, aB[1]);
                aB[2] = fma2(hBd, w23.x, aB[2]);
                aB[3] = fma2(hBd, w23.y, aB[3]);
            }
            {   // k = 2p+1
                const u64 hAd = pk2(ha1, ha1);
                const u64 hBd = pk2(hb1, hb1);
                ulonglong2 w01 = *reinterpret_cast<const ulonglong2*>(wkb + (2*p+1)*32);
                ulonglong2 w23 = *reinterpret_cast<const ulonglong2*>(wkb + (2*p+1)*32 + 4);
                aA[0] = fma2(hAd, w01.x, aA[0]);
                aA[1] = fma2(hAd, w01.y, aA[1]);
                aA[2] = fma2(hAd, w23.x, aA[2]);
                aA[3] = fma2(hAd, w23.y, aA[3]);
                aB[0] = fma2(hBd, w01.x, aB[0]);
                aB[1] = fma2(hBd, w01.y, aB[1]);
                aB[2] = fma2(hBd, w23.x, aB[2]);
                aB[3] = fma2(hBd, w23.y, aB[3]);
            }
        }
        // silu + fold into layer-3 dot (w3 pre-scaled)
        ulonglong2 p01 = *reinterpret_cast<const ulonglong2*>(w3 + ch*8);
        ulonglong2 p23 = *reinterpret_cast<const ulonglong2*>(w3 + ch*8 + 4);
        tA = fma2(silu2p(aA[0]), p01.x, tA);
        tB = fma2(silu2p(aB[0]), p01.x, tB);
        tA = fma2(silu2p(aA[1]), p01.y, tA);
        tB = fma2(silu2p(aB[1]), p01.y, tB);
        tA = fma2(silu2p(aA[2]), p23.x, tA);
        tB = fma2(silu2p(aB[2]), p23.x, tB);
        tA = fma2(silu2p(aA[3]), p23.y, tA);
        tB = fma2(silu2p(aB[3]), p23.y, tB);
    }
    float a0, a1, b0, b1v;
    upk2(tA, a0, a1);
    upk2(tB, b0, b1v);
    kA += silu_fp(a0 + a1 + b3);
    kB += silu_fp(b0 + b1v + b3);
}

__global__ __launch_bounds__(256, 2)
void ema_kernel(const float* __restrict__ g,
                const float* __restrict__ f,
                const int* __restrict__ mask,
                const float* __restrict__ kyW1, const float* __restrict__ kyb1,
                const float* __restrict__ kyW2, const float* __restrict__ kyb2,
                const float* __restrict__ kyW3, const float* __restrict__ kyb3,
                const float* __restrict__ kgW1, const float* __restrict__ kgb1,
                const float* __restrict__ kgW2, const float* __restrict__ kgb2,
                const float* __restrict__ kgW3, const float* __restrict__ kgb3,
                const float* __restrict__ wout,
                float* __restrict__ out)
{
    __shared__ __align__(16) float sw[SWTOT];

    const int tid = threadIdx.x;

    // ---- stage weights: transpose to input-major, pre-scale by 0.5 ----
    {
        for (int idx = tid; idx < 4096; idx += 256) {
            int c = idx >> 10, o = (idx >> 5) & 31, k = idx & 31;
            int d = c * 1024 + k * 32 + o;
            sw[KYW2t + d] = 0.5f * kyW2[idx];
            sw[KGW2t + d] = 0.5f * kgW2[idx];
        }
        for (int idx = tid; idx < 1024; idx += 256) {
            int c = idx >> 8, o = (idx >> 3) & 31, k = idx & 7;
            sw[KGW1t + c * 256 + k * 32 + o] = 0.5f * kgW1[idx];
        }
        if (tid < 256) {
            int idx = tid;
            int c = idx >> 6, o = (idx >> 1) & 31, k = idx & 1;
            sw[KYW1t + c * 64 + k * 32 + o] = 0.5f * kyW1[idx];
        }
        for (int idx = tid; idx < 128; idx += 256) {
            sw[KYB1o + idx] = 0.5f * kyb1[idx];
            sw[KGB1o + idx] = 0.5f * kgb1[idx];
            sw[KYB2o + idx] = 0.5f * kyb2[idx];
            sw[KGB2o + idx] = 0.5f * kgb2[idx];
            sw[KYW3o + idx] = 0.5f * kyW3[idx];
            sw[KGW3o + idx] = 0.5f * kgW3[idx];
        }
        if (tid < 4) { sw[KYB3o + tid] = 0.5f * kyb3[tid]; sw[KGB3o + tid] = 0.5f * kgb3[tid]; }
        if (tid < 32) sw[WOUTo + tid] = wout[tid];
    }
    __syncthreads();

    // ---- decode query (b, i, s) ----
    const int bid = blockIdx.x;
    const int b   = bid >> 9;
    const int rem = bid & 511;
    const int i   = rem >> 2;
    const int s   = rem & 3;

    float fq[CINc];
    {
        const float* fqp = f + (((size_t)b * Nc + i) * Sc + s) * CINc;
        float4 v = *reinterpret_cast<const float4*>(fqp);
        fq[0] = v.x; fq[1] = v.y; fq[2] = v.z; fq[3] = v.w;
    }

    // ---- two keys per thread: A=(j0,t), B=(j0+64,t) ----
    const int j0 = tid >> 2;
    const int t  = tid & 3;
    const int j1 = j0 + 64;

    // pointers (values reloaded per channel to keep registers free)
    const float* gpA = g + ((((((size_t)b * Nc + i) * Nc + j0) * Sc + s) * Sc) + t) * DGc;
    const float* gpB = gpA + (size_t)64 * Sc * Sc * DGc;
    const float* fkpA = f + (((size_t)b * Nc + j0) * Sc + t) * CINc;
    const float* fkpB = f + (((size_t)b * Nc + j1) * Sc + t) * CINc;

    const bool mkA = mask[((size_t)b * Nc + j0) * Sc + t] != 0;
    const bool mkB = mask[((size_t)b * Nc + j1) * Sc + t] != 0;

    float num[CINc], den[CINc];

    #pragma unroll 1
    for (int c = 0; c < CINc; ++c) {
        float kAt = 0.f, kBt = 0.f;
        u64 hpA[16], hpB[16];   // output-packed activations per position

        // per-channel key scalars (reloaded; address depends on c)
        float fkAc, fkBc;
        asm volatile("ld.global.nc.f32 %0, [%1];" : "=f"(fkAc) : "l"(fkpA + c));
        asm volatile("ld.global.nc.f32 %0, [%1];" : "=f"(fkBc) : "l"(fkpB + c));

        #pragma unroll 1
        for (int m = 0; m < 2; ++m) {
            // ===== layer 1 (output-packed, non-dup weights) =====
            if (m == 0) {
                const float* w1 = sw + KYW1t + c * 64;   // [k2][o]
                const float* b1 = sw + KYB1o + c * 32;
                const u64 fqd  = pk2(fq[c], fq[c]);
                const u64 fkAd = pk2(fkAc, fkAc);
                const u64 fkBd = pk2(fkBc, fkBc);
                #pragma unroll
                for (int q = 0; q < 8; ++q) {
                    ulonglong2 w0 = *reinterpret_cast<const ulonglong2*>(w1 + 4*q);       // k=0 (key)
                    ulonglong2 wq = *reinterpret_cast<const ulonglong2*>(w1 + 32 + 4*q);  // k=1 (query)
                    ulonglong2 bv = *reinterpret_cast<const ulonglong2*>(b1 + 4*q);
                    u64 t0 = fma2(fqd, wq.x, bv.x);
                    u64 t1 = fma2(fqd, wq.y, bv.y);
                    hpA[2*q]   = fma2(fkAd, w0.x, t0);
                    hpA[2*q+1] = fma2(fkAd, w0.y, t1);
                    hpB[2*q]   = fma2(fkBd, w0.x, t0);
                    hpB[2*q+1] = fma2(fkBd, w0.y, t1);
                }
            } else {
                // reload g per channel (volatile: keep out of persistent regs)
                float gA[DGc], gB[DGc];
                asm volatile("ld.global.nc.v4.f32 {%0,%1,%2,%3}, [%4];"
                             : "=f"(gA[0]), "=f"(gA[1]), "=f"(gA[2]), "=f"(gA[3]) : "l"(gpA));
                asm volatile("ld.global.nc.v4.f32 {%0,%1,%2,%3}, [%4];"
                             : "=f"(gA[4]), "=f"(gA[5]), "=f"(gA[6]), "=f"(gA[7]) : "l"(gpA + 4));
                asm volatile("ld.global.nc.v4.f32 {%0,%1,%2,%3}, [%4];"
                             : "=f"(gB[0]), "=f"(gB[1]), "=f"(gB[2]), "=f"(gB[3]) : "l"(gpB));
                asm volatile("ld.global.nc.v4.f32 {%0,%1,%2,%3}, [%4];"
                             : "=f"(gB[4]), "=f"(gB[5]), "=f"(gB[6]), "=f"(gB[7]) : "l"(gpB + 4));

                const float* w1 = sw + KGW1t + c * 256;   // [k8][o]
                const float* b1 = sw + KGB1o + c * 32;
                #pragma unroll
                for (int q = 0; q < 8; ++q) {
                    ulonglong2 bv = *reinterpret_cast<const ulonglong2*>(b1 + 4*q);
                    hpA[2*q] = bv.x; hpA[2*q+1] = bv.y;
                    hpB[2*q] = bv.x; hpB[2*q+1] = bv.y;
                }
                #pragma unroll
                for (int k = 0; k < DGc; ++k) {
                    const u64 gad = pk2(gA[k], gA[k]);
                    const u64 gbd = pk2(gB[k], gB[k]);
                    const float* wk = w1 + k * 32;
                    #pragma unroll
                    for (int q = 0; q < 8; ++q) {
                        ulonglong2 wv = *reinterpret_cast<const ulonglong2*>(wk + 4*q);
                        hpA[2*q]   = fma2(gad, wv.x, hpA[2*q]);
                        hpA[2*q+1] = fma2(gad, wv.y, hpA[2*q+1]);
                        hpB[2*q]   = fma2(gbd, wv.x, hpB[2*q]);
                        hpB[2*q+1] = fma2(gbd, wv.y, hpB[2*q+1]);
                    }
                }
            }
            // silu (pre-scaled form)
            #pragma unroll
            for (int p = 0; p < 16; ++p) {
                hpA[p] = silu2p(hpA[p]);
                hpB[p] = silu2p(hpB[p]);
            }

            // ===== fused layers 2+3 =====
            mlp23(hpA, hpB,
                  sw + (m ? KGW2t : KYW2t) + c * 1024,
                  sw + (m ? KGB2o : KYB2o) + c * HIDc,
                  sw + (m ? KGW3o : KYW3o) + c * HIDc,
                  sw[(m ? KGB3o : KYB3o) + c], kAt, kBt);
        }

        const float eA = mkA ? ex2f(LOG2E * kAt) : 0.0f;
        const float eB = mkB ? ex2f(LOG2E * kBt) : 0.0f;
        den[c] = eA + eB;
        num[c] = fmaf(eA, fkAc, eB * fkBc);
    }

    // ---- reduce over 256 threads (8 warps) ----
    #pragma unroll
    for (int c = 0; c < CINc; ++c) {
        #pragma unroll
        for (int off = 16; off > 0; off >>= 1) {
            num[c] += __shfl_xor_sync(0xFFFFFFFFu, num[c], off);
            den[c] += __shfl_xor_sync(0xFFFFFFFFu, den[c], off);
        }
    }
    const int wid = tid >> 5;
    const int lid = tid & 31;
    if (lid == 0) {
        #pragma unroll
        for (int c = 0; c < CINc; ++c) {
            sw[SREDo + wid * 8 + c]     = num[c];
            sw[SREDo + wid * 8 + 4 + c] = den[c];
        }
    }
    __syncthreads();

    if (tid < COUTc) {
        const int o = tid;
        const float mq = (mask[((size_t)b * Nc + i) * Sc + s] != 0) ? 1.0f : 0.0f;
        float acc = 0.0f;
        #pragma unroll
        for (int c = 0; c < CINc; ++c) {
            float n = 0.0f, d = 0.0f;
            #pragma unroll
            for (int w = 0; w < 8; ++w) {
                n += sw[SREDo + w * 8 + c];
                d += sw[SREDo + w * 8 + 4 + c];
            }
            const float cf = (fq[c] + n / d) * mq;
            acc = fmaf(cf, sw[WOUTo + o * CINc + c], acc);
        }
        out[(((size_t)b * Nc + i) * Sc + s) * COUTc + o] = acc;
    }
}

extern "C" void kernel_launch(void* const* d_in, const int* in_sizes, int n_in,
                              void* d_out, int out_size)
{
    const float* g    = (const float*)d_in[0];
    const float* f    = (const float*)d_in[1];
    const int*   mask = (const int*)d_in[2];
    const float* kyW1 = (const float*)d_in[3];
    const float* kyb1 = (const float*)d_in[4];
    const float* kyW2 = (const float*)d_in[5];
    const float* kyb2 = (const float*)d_in[6];
    const float* kyW3 = (const float*)d_in[7];
    const float* kyb3 = (const float*)d_in[8];
    const float* kgW1 = (const float*)d_in[9];
    const float* kgb1 = (const float*)d_in[10];
    const float* kgW2 = (const float*)d_in[11];
    const float* kgb2 = (const float*)d_in[12];
    const float* kgW3 = (const float*)d_in[13];
    const float* kgb3 = (const float*)d_in[14];
    const float* wout = (const float*)d_in[15];
    float* out = (float*)d_out;

    ema_kernel<<<Bc * Nc * Sc, 256>>>(g, f, mask,
                                      kyW1, kyb1, kyW2, kyb2, kyW3, kyb3,
                                      kgW1, kgb1, kgW2, kgb2, kgW3, kgb3,
                                      wout, out);
}

// round 13
// speedup vs baseline: 1.2860x; 1.2860x over previous
#include <cuda_runtime.h>
#include <cuda_bf16.h>
#include <cstdint>

#define Bc    2
#define Nc    128
#define Sc    4
#define DGc   8
#define CINc  4
#define COUTc 8
#define HIDc  32

// Dynamic smem:
// [0, 73728): h-buffer, 512 rows x 144B stride.
//   Row kappa: bytes [0,64) = hi bf16[dim 0..31], [64,128) = lo bf16, [128,144) pad.
//   144B stride => rows 0..7 start at banks 4r mod 32: ldmatrix phases and
//   STS.128 phases are conflict-free.
// floats at +73728: layer-1 weights (input-major, x0.5), biases/w3 (x0.5), wout.
#define HBUF_BYTES 73728
#define KYW1t 0        // [c][k2][o]  256
#define KGW1t 256      // [c][k8][o]  1024
#define KYB1  1280     // 128
#define KGB1  1408     // 128
#define KYB2  1536     // 128 (x0.5)
#define KGB2  1664     // 128
#define KYW3  1792     // 128 (x0.5)
#define KGW3  1920     // 128
#define KYB3  2048     // 4
#define KGB3  2052     // 4
#define WOUT  2056     // 32
#define SRED  2088     // 64
#define SF_FLOATS 2152
#define SMEM_BYTES (HBUF_BYTES + SF_FLOATS * 4)

typedef unsigned long long u64;

__device__ __forceinline__ u64 pk2(float lo, float hi) {
    u64 r; asm("mov.b64 %0, {%1, %2};" : "=l"(r) : "f"(lo), "f"(hi)); return r;
}
__device__ __forceinline__ void upk2(u64 v, float& lo, float& hi) {
    asm("mov.b64 {%0, %1}, %2;" : "=f"(lo), "=f"(hi) : "l"(v));
}
__device__ __forceinline__ u64 fma2(u64 a, u64 b, u64 c) {
    u64 d; asm("fma.rn.f32x2 %0, %1, %2, %3;" : "=l"(d) : "l"(a), "l"(b), "l"(c)); return d;
}
__device__ __forceinline__ u64 add2(u64 a, u64 b) {
    u64 d; asm("add.rn.f32x2 %0, %1, %2;" : "=l"(d) : "l"(a), "l"(b)); return d;
}
__device__ __forceinline__ float ex2f(float x) {
    float r; asm("ex2.approx.f32 %0, %1;" : "=f"(r) : "f"(x)); return r;
}
__device__ __forceinline__ float tanhf_a(float x) {
    float r; asm("tanh.approx.f32 %0, %1;" : "=f"(r) : "f"(x)); return r;
}

#define LOG2E 1.4426950408889634f

__device__ __forceinline__ u64 silu2p(u64 acc) {   // acc = x/2 -> silu(x)
    float a, b; upk2(acc, a, b);
    return fma2(acc, pk2(tanhf_a(a), tanhf_a(b)), acc);
}
__device__ __forceinline__ float silu_fp(float acc) {
    return fmaf(acc, tanhf_a(acc), acc);
}

// pack two f32 to bf16x2: low half = lo, high half = hi
__device__ __forceinline__ uint32_t cvt_bf2(float lo, float hi) {
    uint32_t r; asm("cvt.rn.bf16x2.f32 %0, %1, %2;" : "=r"(r) : "f"(hi), "f"(lo)); return r;
}
__device__ __forceinline__ float bfl(uint32_t h) { return __uint_as_float(h << 16); }
__device__ __forceinline__ float bfh(uint32_t h) { return __uint_as_float(h & 0xFFFF0000u); }

__device__ __forceinline__ uint32_t smem_u32(const void* p) {
    uint32_t a;
    asm("{ .reg .u64 t; cvta.to.shared.u64 t, %1; cvt.u32.u64 %0, t; }" : "=r"(a) : "l"(p));
    return a;
}

__device__ __forceinline__ void ldmx4(uint32_t* r, uint32_t addr) {
    asm volatile("ldmatrix.sync.aligned.m8n8.x4.shared.b16 {%0,%1,%2,%3}, [%4];"
                 : "=r"(r[0]), "=r"(r[1]), "=r"(r[2]), "=r"(r[3]) : "r"(addr));
}

__device__ __forceinline__ void mma16816(float* d, const uint32_t* a,
                                         uint32_t b0, uint32_t b1) {
    asm volatile("mma.sync.aligned.m16n8k16.row.col.f32.bf16.bf16.f32 "
                 "{%0,%1,%2,%3}, {%4,%5,%6,%7}, {%8,%9}, {%0,%1,%2,%3};"
                 : "+f"(d[0]), "+f"(d[1]), "+f"(d[2]), "+f"(d[3])
                 : "r"(a[0]), "r"(a[1]), "r"(a[2]), "r"(a[3]), "r"(b0), "r"(b1));
}

__global__ __launch_bounds__(256, 2)
void ema_kernel(const float* __restrict__ g,
                const float* __restrict__ f,
                const int* __restrict__ mask,
                const float* __restrict__ kyW1, const float* __restrict__ kyb1,
                const float* __restrict__ kyW2, const float* __restrict__ kyb2,
                const float* __restrict__ kyW3, const float* __restrict__ kyb3,
                const float* __restrict__ kgW1, const float* __restrict__ kgb1,
                const float* __restrict__ kgW2, const float* __restrict__ kgb2,
                const float* __restrict__ kgW3, const float* __restrict__ kgb3,
                const float* __restrict__ wout,
                float* __restrict__ out)
{
    extern __shared__ __align__(16) char dsm[];
    float* sf = reinterpret_cast<float*>(dsm + HBUF_BYTES);

    const int tid  = threadIdx.x;
    const int w    = tid >> 5;
    const int lane = tid & 31;
    const int gq   = lane >> 2;        // quad group id = fragment row within tile

    // ---- stage layer-1 weights / biases / w3 (all x0.5, input-major) ----
    for (int idx = tid; idx < 1024; idx += 256) {
        int c = idx >> 8, o = (idx >> 3) & 31, k = idx & 7;
        sf[KGW1t + c * 256 + k * 32 + o] = 0.5f * kgW1[idx];
    }
    {
        int c = tid >> 6, o = (tid >> 1) & 31, k = tid & 1;
        sf[KYW1t + c * 64 + k * 32 + o] = 0.5f * kyW1[tid];
    }
    for (int idx = tid; idx < 128; idx += 256) {
        sf[KYB1 + idx] = 0.5f * kyb1[idx];
        sf[KGB1 + idx] = 0.5f * kgb1[idx];
        sf[KYB2 + idx] = 0.5f * kyb2[idx];
        sf[KGB2 + idx] = 0.5f * kgb2[idx];
        sf[KYW3 + idx] = 0.5f * kyW3[idx];
        sf[KGW3 + idx] = 0.5f * kgW3[idx];
    }
    if (tid < 4) { sf[KYB3 + tid] = 0.5f * kyb3[tid]; sf[KGB3 + tid] = 0.5f * kgb3[tid]; }
    if (tid < 32) sf[WOUT + tid] = wout[tid];

    // ---- decode query (b, i, s) ----
    const int bid = blockIdx.x;
    const int b   = bid >> 9;
    const int rem = bid & 511;
    const int i   = rem >> 2;
    const int s   = rem & 3;

    float fq[CINc];
    {
        float4 v = *reinterpret_cast<const float4*>(f + (((size_t)b * Nc + i) * Sc + s) * CINc);
        fq[0] = v.x; fq[1] = v.y; fq[2] = v.z; fq[3] = v.w;
    }

    // ---- layer-1 keys owned by this thread: rows kappa = tid and tid+256 ----
    const int j0 = tid >> 2;
    const int t  = tid & 3;

    float gA[DGc], gB[DGc];
    {
        const float* gp = g + ((((((size_t)b * Nc + i) * Nc + j0) * Sc + s) * Sc) + t) * DGc;
        float4 g0 = *reinterpret_cast<const float4*>(gp);
        float4 g1 = *reinterpret_cast<const float4*>(gp + 4);
        gA[0]=g0.x; gA[1]=g0.y; gA[2]=g0.z; gA[3]=g0.w;
        gA[4]=g1.x; gA[5]=g1.y; gA[6]=g1.z; gA[7]=g1.w;
        const float* gp2 = gp + (size_t)64 * Sc * Sc * DGc;
        float4 h0 = *reinterpret_cast<const float4*>(gp2);
        float4 h1 = *reinterpret_cast<const float4*>(gp2 + 4);
        gB[0]=h0.x; gB[1]=h0.y; gB[2]=h0.z; gB[3]=h0.w;
        gB[4]=h1.x; gB[5]=h1.y; gB[6]=h1.z; gB[7]=h1.w;
    }
    float fkA[CINc], fkB[CINc];
    {
        float4 v = *reinterpret_cast<const float4*>(f + ((size_t)b * 512 + tid) * CINc);
        fkA[0]=v.x; fkA[1]=v.y; fkA[2]=v.z; fkA[3]=v.w;
        float4 x = *reinterpret_cast<const float4*>(f + ((size_t)b * 512 + tid + 256) * CINc);
        fkB[0]=x.x; fkB[1]=x.y; fkB[2]=x.z; fkB[3]=x.w;
    }

    // ---- epilogue keys for this thread: kappa = 64w + 16T + gq (+8), T=0..3 ----
    int mks[8];
    #pragma unroll
    for (int T = 0; T < 4; ++T) {
        int kap = 64 * w + 16 * T + gq;
        mks[2*T]   = mask[(size_t)b * 512 + kap];
        mks[2*T+1] = mask[(size_t)b * 512 + kap + 8];
    }

    __syncthreads();

    const uint32_t hb = smem_u32(dsm);
    float num[CINc], den[CINc];

    #pragma unroll 1
    for (int c = 0; c < CINc; ++c) {
        float kk[8];
        #pragma unroll
        for (int q = 0; q < 8; ++q) kk[q] = 0.f;

        #pragma unroll 1
        for (int m = 0; m < 2; ++m) {
            // ===== layer 1 (scalar f32x2, output-packed pairs) =====
            u64 hpA[16], hpB[16];
            if (m == 0) {
                const float* w1 = sf + KYW1t + c * 64;
                const float* b1 = sf + KYB1 + c * 32;
                const u64 fqd  = pk2(fq[c], fq[c]);
                const u64 fkAd = pk2(fkA[c], fkA[c]);
                const u64 fkBd = pk2(fkB[c], fkB[c]);
                #pragma unroll
                for (int q = 0; q < 8; ++q) {
                    ulonglong2 w0 = *reinterpret_cast<const ulonglong2*>(w1 + 4*q);
                    ulonglong2 wq = *reinterpret_cast<const ulonglong2*>(w1 + 32 + 4*q);
                    ulonglong2 bv = *reinterpret_cast<const ulonglong2*>(b1 + 4*q);
                    u64 t0 = fma2(fqd, wq.x, bv.x);
                    u64 t1 = fma2(fqd, wq.y, bv.y);
                    hpA[2*q]   = fma2(fkAd, w0.x, t0);
                    hpA[2*q+1] = fma2(fkAd, w0.y, t1);
                    hpB[2*q]   = fma2(fkBd, w0.x, t0);
                    hpB[2*q+1] = fma2(fkBd, w0.y, t1);
                }
            } else {
                const float* w1 = sf + KGW1t + c * 256;
                const float* b1 = sf + KGB1 + c * 32;
                #pragma unroll
                for (int q = 0; q < 8; ++q) {
                    ulonglong2 bv = *reinterpret_cast<const ulonglong2*>(b1 + 4*q);
                    hpA[2*q] = bv.x; hpA[2*q+1] = bv.y;
                    hpB[2*q] = bv.x; hpB[2*q+1] = bv.y;
                }
                #pragma unroll
                for (int k = 0; k < DGc; ++k) {
                    const u64 gad = pk2(gA[k], gA[k]);
                    const u64 gbd = pk2(gB[k], gB[k]);
                    const float* wk = w1 + k * 32;
                    #pragma unroll
                    for (int q = 0; q < 8; ++q) {
                        ulonglong2 wv = *reinterpret_cast<const ulonglong2*>(wk + 4*q);
                        hpA[2*q]   = fma2(gad, wv.x, hpA[2*q]);
                        hpA[2*q+1] = fma2(gad, wv.y, hpA[2*q+1]);
                        hpB[2*q]   = fma2(gbd, wv.x, hpB[2*q]);
                        hpB[2*q+1] = fma2(gbd, wv.y, hpB[2*q+1]);
                    }
                }
            }
            #pragma unroll
            for (int p = 0; p < 16; ++p) { hpA[p] = silu2p(hpA[p]); hpB[p] = silu2p(hpB[p]); }

            // ===== cvt to bf16 hi/lo and STS rows tid, tid+256 =====
            {
                uint32_t hi[16], lo[16];
                #pragma unroll
                for (int p = 0; p < 16; ++p) {
                    float e0, e1; upk2(hpA[p], e0, e1);
                    uint32_t h = cvt_bf2(e0, e1);
                    hi[p] = h;
                    lo[p] = cvt_bf2(e0 - bfl(h), e1 - bfh(h));
                }
                char* rp = dsm + tid * 144;
                #pragma unroll
                for (int q = 0; q < 4; ++q) {
                    *reinterpret_cast<uint4*>(rp + q * 16) =
                        make_uint4(hi[4*q], hi[4*q+1], hi[4*q+2], hi[4*q+3]);
                    *reinterpret_cast<uint4*>(rp + 64 + q * 16) =
                        make_uint4(lo[4*q], lo[4*q+1], lo[4*q+2], lo[4*q+3]);
                }
                #pragma unroll
                for (int p = 0; p < 16; ++p) {
                    float e0, e1; upk2(hpB[p], e0, e1);
                    uint32_t h = cvt_bf2(e0, e1);
                    hi[p] = h;
                    lo[p] = cvt_bf2(e0 - bfl(h), e1 - bfh(h));
                }
                rp = dsm + (tid + 256) * 144;
                #pragma unroll
                for (int q = 0; q < 4; ++q) {
                    *reinterpret_cast<uint4*>(rp + q * 16) =
                        make_uint4(hi[4*q], hi[4*q+1], hi[4*q+2], hi[4*q+3]);
                    *reinterpret_cast<uint4*>(rp + 64 + q * 16) =
                        make_uint4(lo[4*q], lo[4*q+1], lo[4*q+2], lo[4*q+3]);
                }
            }
            __syncthreads();

            // ===== B fragments from global W2 (x0.5, bf16 hi/lo) =====
            const float* W2g = (m ? kgW2 : kyW2) + c * 1024;
            uint32_t bh[2][4][2], bl[2][4][2];
            {
                const int o  = (lane >> 2);            // + nt*8
                const int kb = (lane & 3) * 2;         // + q*16 (+8 for b1)
                #pragma unroll
                for (int q = 0; q < 2; ++q) {
                    #pragma unroll
                    for (int nt = 0; nt < 4; ++nt) {
                        const float* base = W2g + (nt * 8 + o) * 32 + q * 16 + kb;
                        float2 w0 = *reinterpret_cast<const float2*>(base);
                        float2 w1 = *reinterpret_cast<const float2*>(base + 8);
                        float x0 = 0.5f * w0.x, x1 = 0.5f * w0.y;
                        uint32_t h0 = cvt_bf2(x0, x1);
                        bh[q][nt][0] = h0;
                        bl[q][nt][0] = cvt_bf2(x0 - bfl(h0), x1 - bfh(h0));
                        float y0 = 0.5f * w1.x, y1 = 0.5f * w1.y;
                        uint32_t h1 = cvt_bf2(y0, y1);
                        bh[q][nt][1] = h1;
                        bl[q][nt][1] = cvt_bf2(y0 - bfl(h1), y1 - bfh(h1));
                    }
                }
            }

            // ===== per-tile: ldmatrix A, 24 MMAs, epilogue =====
            const float* b2 = sf + (m ? KGB2 : KYB2) + c * HIDc;
            const float* w3 = sf + (m ? KGW3 : KYW3) + c * HIDc;
            const float  b3 = sf[(m ? KGB3 : KYB3) + c];
            const uint32_t lmbase = hb
                + (uint32_t)(64 * w + (lane & 7) + ((lane >> 3) & 1) * 8) * 144
                + ((lane >> 4) & 1) * 16;

            #pragma unroll 1
            for (int T = 0; T < 4; ++T) {
                uint32_t ahi[2][4], alo[2][4];
                const uint32_t ab = lmbase + (uint32_t)(16 * T) * 144;
                ldmx4(ahi[0], ab);
                ldmx4(ahi[1], ab + 32);
                ldmx4(alo[0], ab + 64);
                ldmx4(alo[1], ab + 96);

                float d[4][4];
                #pragma unroll
                for (int nt = 0; nt < 4; ++nt)
                    d[nt][0] = d[nt][1] = d[nt][2] = d[nt][3] = 0.f;

                #pragma unroll
                for (int q = 0; q < 2; ++q) {
                    #pragma unroll
                    for (int nt = 0; nt < 4; ++nt)
                        mma16816(d[nt], ahi[q], bh[q][nt][0], bh[q][nt][1]);
                    #pragma unroll
                    for (int nt = 0; nt < 4; ++nt)
                        mma16816(d[nt], alo[q], bh[q][nt][0], bh[q][nt][1]);
                    #pragma unroll
                    for (int nt = 0; nt < 4; ++nt)
                        mma16816(d[nt], ahi[q], bl[q][nt][0], bl[q][nt][1]);
                }

                // epilogue: rows gq, gq+8; cols nt*8 + (lane&3)*2, +1
                u64 t0 = pk2(0.f, 0.f), t1 = pk2(0.f, 0.f);
                const int co = (lane & 3) * 2;
                #pragma unroll
                for (int nt = 0; nt < 4; ++nt) {
                    u64 bb = *reinterpret_cast<const u64*>(b2 + nt * 8 + co);
                    u64 ww = *reinterpret_cast<const u64*>(w3 + nt * 8 + co);
                    t0 = fma2(silu2p(add2(pk2(d[nt][0], d[nt][1]), bb)), ww, t0);
                    t1 = fma2(silu2p(add2(pk2(d[nt][2], d[nt][3]), bb)), ww, t1);
                }
                float s0a, s0b, s1a, s1b;
                upk2(t0, s0a, s0b);
                upk2(t1, s1a, s1b);
                float s0 = s0a + s0b, s1 = s1a + s1b;
                s0 += __shfl_xor_sync(0xFFFFFFFFu, s0, 1);
                s0 += __shfl_xor_sync(0xFFFFFFFFu, s0, 2);
                s1 += __shfl_xor_sync(0xFFFFFFFFu, s1, 1);
                s1 += __shfl_xor_sync(0xFFFFFFFFu, s1, 2);
                kk[2*T]   += silu_fp(s0 + b3);
                kk[2*T+1] += silu_fp(s1 + b3);
            }
            __syncthreads();   // before next round overwrites h-buffer
        }

        // ===== exp + mask + num/den over this thread's 8 epilogue keys =====
        float nc = 0.f, dc = 0.f;
        #pragma unroll
        for (int T = 0; T < 4; ++T) {
            int kap = 64 * w + 16 * T + gq;
            float fk0 = f[((size_t)b * 512 + kap) * CINc + c];
            float fk1 = f[((size_t)b * 512 + kap + 8) * CINc + c];
            float e0 = mks[2*T]   ? ex2f(LOG2E * kk[2*T])   : 0.f;
            float e1 = mks[2*T+1] ? ex2f(LOG2E * kk[2*T+1]) : 0.f;
            dc += e0 + e1;
            nc += fmaf(e0, fk0, e1 * fk1);
        }
        num[c] = nc;
        den[c] = dc;
    }

    // ---- reduce over 256 threads (quad replication x4 cancels in n/d) ----
    #pragma unroll
    for (int c = 0; c < CINc; ++c) {
        #pragma unroll
        for (int off = 16; off > 0; off >>= 1) {
            num[c] += __shfl_xor_sync(0xFFFFFFFFu, num[c], off);
            den[c] += __shfl_xor_sync(0xFFFFFFFFu, den[c], off);
        }
    }
    if (lane == 0) {
        #pragma unroll
        for (int c = 0; c < CINc; ++c) {
            sf[SRED + w * 8 + c]     = num[c];
            sf[SRED + w * 8 + 4 + c] = den[c];
        }
    }
    __syncthreads();

    if (tid < COUTc) {
        const int o = tid;
        const float mq = (mask[((size_t)b * Nc + i) * Sc + s] != 0) ? 1.0f : 0.0f;
        float acc = 0.0f;
        #pragma unroll
        for (int c = 0; c < CINc; ++c) {
            float n = 0.0f, d = 0.0f;
            #pragma unroll
            for (int ww = 0; ww < 8; ++ww) {
                n += sf[SRED + ww * 8 + c];
                d += sf[SRED + ww * 8 + 4 + c];
            }
            const float cf = (fq[c] + n / d) * mq;
            acc = fmaf(cf, sf[WOUT + o * CINc + c], acc);
        }
        out[(((size_t)b * Nc + i) * Sc + s) * COUTc + o] = acc;
    }
}

extern "C" void kernel_launch(void* const* d_in, const int* in_sizes, int n_in,
                              void* d_out, int out_size)
{
    const float* g    = (const float*)d_in[0];
    const float* f    = (const float*)d_in[1];
    const int*   mask = (const int*)d_in[2];
    const float* kyW1 = (const float*)d_in[3];
    const float* kyb1 = (const float*)d_in[4];
    const float* kyW2 = (const float*)d_in[5];
    const float* kyb2 = (const float*)d_in[6];
    const float* kyW3 = (const float*)d_in[7];
    const float* kyb3 = (const float*)d_in[8];
    const float* kgW1 = (const float*)d_in[9];
    const float* kgb1 = (const float*)d_in[10];
    const float* kgW2 = (const float*)d_in[11];
    const float* kgb2 = (const float*)d_in[12];
    const float* kgW3 = (const float*)d_in[13];
    const float* kgb3 = (const float*)d_in[14];
    const float* wout = (const float*)d_in[15];
    float* out = (float*)d_out;

    cudaFuncSetAttribute(ema_kernel, cudaFuncAttributeMaxDynamicSharedMemorySize, SMEM_BYTES);
    ema_kernel<<<Bc * Nc * Sc, 256, SMEM_BYTES>>>(g, f, mask,
                                      kyW1, kyb1, kyW2, kyb2, kyW3, kyb3,
                                      kgW1, kgb1, kgW2, kgb2, kgW3, kgb3,
                                      wout, out);
}

// round 14
// speedup vs baseline: 1.3296x; 1.0339x over previous
#include <cuda_runtime.h>
#include <cuda_bf16.h>
#include <cstdint>

#define Bc    2
#define Nc    128
#define Sc    4
#define DGc   8
#define CINc  4
#define COUTc 8
#define HIDc  32

// Dynamic smem:
// [0, 73728): h-buffer, 512 rows x 144B stride (hi bf16 [0,64), lo bf16 [64,128), pad).
// [73728, 106496): pre-split B fragments: 8 rounds x 4KB.
//   round r = c*2+m; value j (0..15 = bh, 16..31 = bl), j-sub = q*8+nt*2+pair;
//   addr = BFR + r*4096 + (j>>2)*512 + lane*16 + (j&3)*4  -> 8 conflict-free LDS.128/lane.
// floats at +106496: layer-1 weights (input-major, x0.5), biases/w3 (x0.5), wout.
#define HBUF_BYTES 73728
#define BFR 73728
#define SFOFF 106496
#define KYW1t 0        // [c][k2][o]  256
#define KGW1t 256      // [c][k8][o]  1024
#define KYB1  1280     // 128
#define KGB1  1408     // 128
#define KYB2  1536     // 128 (x0.5)
#define KGB2  1664     // 128
#define KYW3  1792     // 128 (x0.5)
#define KGW3  1920     // 128
#define KYB3  2048     // 4
#define KGB3  2052     // 4
#define WOUT  2056     // 32
#define SRED  2088     // 64
#define SF_FLOATS 2152
#define SMEM_BYTES (SFOFF + SF_FLOATS * 4)

typedef unsigned long long u64;

__device__ __forceinline__ u64 pk2(float lo, float hi) {
    u64 r; asm("mov.b64 %0, {%1, %2};" : "=l"(r) : "f"(lo), "f"(hi)); return r;
}
__device__ __forceinline__ void upk2(u64 v, float& lo, float& hi) {
    asm("mov.b64 {%0, %1}, %2;" : "=f"(lo), "=f"(hi) : "l"(v));
}
__device__ __forceinline__ u64 fma2(u64 a, u64 b, u64 c) {
    u64 d; asm("fma.rn.f32x2 %0, %1, %2, %3;" : "=l"(d) : "l"(a), "l"(b), "l"(c)); return d;
}
__device__ __forceinline__ u64 add2(u64 a, u64 b) {
    u64 d; asm("add.rn.f32x2 %0, %1, %2;" : "=l"(d) : "l"(a), "l"(b)); return d;
}
__device__ __forceinline__ float ex2f(float x) {
    float r; asm("ex2.approx.f32 %0, %1;" : "=f"(r) : "f"(x)); return r;
}
__device__ __forceinline__ float tanhf_a(float x) {
    float r; asm("tanh.approx.f32 %0, %1;" : "=f"(r) : "f"(x)); return r;
}

#define LOG2E 1.4426950408889634f

__device__ __forceinline__ u64 silu2p(u64 acc) {   // acc = x/2 -> silu(x)
    float a, b; upk2(acc, a, b);
    return fma2(acc, pk2(tanhf_a(a), tanhf_a(b)), acc);
}
__device__ __forceinline__ float silu_fp(float acc) {
    return fmaf(acc, tanhf_a(acc), acc);
}

// pack two f32 to bf16x2: low half = lo arg, high half = hi arg
__device__ __forceinline__ uint32_t cvt_bf2(float lo, float hi) {
    uint32_t r; asm("cvt.rn.bf16x2.f32 %0, %1, %2;" : "=r"(r) : "f"(hi), "f"(lo)); return r;
}
__device__ __forceinline__ float bfl(uint32_t h) { return __uint_as_float(h << 16); }
__device__ __forceinline__ float bfh(uint32_t h) { return __uint_as_float(h & 0xFFFF0000u); }

__device__ __forceinline__ uint32_t smem_u32(const void* p) {
    uint32_t a;
    asm("{ .reg .u64 t; cvta.to.shared.u64 t, %1; cvt.u32.u64 %0, t; }" : "=r"(a) : "l"(p));
    return a;
}

__device__ __forceinline__ void ldmx4(uint32_t* r, uint32_t addr) {
    asm volatile("ldmatrix.sync.aligned.m8n8.x4.shared.b16 {%0,%1,%2,%3}, [%4];"
                 : "=r"(r[0]), "=r"(r[1]), "=r"(r[2]), "=r"(r[3]) : "r"(addr));
}

__device__ __forceinline__ void mma16816(float* d, const uint32_t* a,
                                         uint32_t b0, uint32_t b1) {
    asm volatile("mma.sync.aligned.m16n8k16.row.col.f32.bf16.bf16.f32 "
                 "{%0,%1,%2,%3}, {%4,%5,%6,%7}, {%8,%9}, {%0,%1,%2,%3};"
                 : "+f"(d[0]), "+f"(d[1]), "+f"(d[2]), "+f"(d[3])
                 : "r"(a[0]), "r"(a[1]), "r"(a[2]), "r"(a[3]), "r"(b0), "r"(b1));
}

__global__ __launch_bounds__(256, 2)
void ema_kernel(const float* __restrict__ g,
                const float* __restrict__ f,
                const int* __restrict__ mask,
                const float* __restrict__ kyW1, const float* __restrict__ kyb1,
                const float* __restrict__ kyW2, const float* __restrict__ kyb2,
                const float* __restrict__ kyW3, const float* __restrict__ kyb3,
                const float* __restrict__ kgW1, const float* __restrict__ kgb1,
                const float* __restrict__ kgW2, const float* __restrict__ kgb2,
                const float* __restrict__ kgW3, const float* __restrict__ kgb3,
                const float* __restrict__ wout,
                float* __restrict__ out)
{
    extern __shared__ __align__(16) char dsm[];
    float* sf = reinterpret_cast<float*>(dsm + SFOFF);

    const int tid  = threadIdx.x;
    const int w    = tid >> 5;
    const int lane = tid & 31;
    const int gq   = lane >> 2;

    // ---- stage layer-1 weights / biases / w3 (all x0.5, input-major) ----
    for (int idx = tid; idx < 1024; idx += 256) {
        int c = idx >> 8, o = (idx >> 3) & 31, k = idx & 7;
        sf[KGW1t + c * 256 + k * 32 + o] = 0.5f * kgW1[idx];
    }
    {
        int c = tid >> 6, o = (tid >> 1) & 31, k = tid & 1;
        sf[KYW1t + c * 64 + k * 32 + o] = 0.5f * kyW1[tid];
    }
    for (int idx = tid; idx < 128; idx += 256) {
        sf[KYB1 + idx] = 0.5f * kyb1[idx];
        sf[KGB1 + idx] = 0.5f * kgb1[idx];
        sf[KYB2 + idx] = 0.5f * kyb2[idx];
        sf[KGB2 + idx] = 0.5f * kgb2[idx];
        sf[KYW3 + idx] = 0.5f * kyW3[idx];
        sf[KGW3 + idx] = 0.5f * kgW3[idx];
    }
    if (tid < 4) { sf[KYB3 + tid] = 0.5f * kyb3[tid]; sf[KGB3 + tid] = 0.5f * kgb3[tid]; }
    if (tid < 32) sf[WOUT + tid] = wout[tid];

    // ---- stage pre-split B fragments: 8 rounds x 32 lanes x 16 hi/lo pairs ----
    for (int idx = tid; idx < 4096; idx += 256) {
        int r  = idx >> 9, rem = idx & 511, ln = rem >> 4, jj = rem & 15;
        int cc = r >> 1,  mm  = r & 1;
        int q  = jj >> 3, nt  = (jj >> 1) & 3, pr = jj & 1;
        const float* W2 = (mm ? kgW2 : kyW2) + cc * 1024;
        int o = nt * 8 + (ln >> 2);
        int k = q * 16 + pr * 8 + (ln & 3) * 2;
        float v0 = 0.5f * W2[o * 32 + k];
        float v1 = 0.5f * W2[o * 32 + k + 1];
        uint32_t hi = cvt_bf2(v0, v1);
        uint32_t lo = cvt_bf2(v0 - bfl(hi), v1 - bfh(hi));
        char* base = dsm + BFR + r * 4096 + ln * 16 + (jj & 3) * 4;
        *reinterpret_cast<uint32_t*>(base + (jj >> 2) * 512)       = hi;
        *reinterpret_cast<uint32_t*>(base + ((jj >> 2) + 4) * 512) = lo;
    }

    // ---- decode query (b, i, s) ----
    const int bid = blockIdx.x;
    const int b   = bid >> 9;
    const int rem = bid & 511;
    const int i   = rem >> 2;
    const int s   = rem & 3;

    float fq[CINc];
    {
        float4 v = *reinterpret_cast<const float4*>(f + (((size_t)b * Nc + i) * Sc + s) * CINc);
        fq[0] = v.x; fq[1] = v.y; fq[2] = v.z; fq[3] = v.w;
    }

    // ---- layer-1 keys owned by this thread: rows kappa = tid and tid+256 ----
    const int j0 = tid >> 2;
    const int t  = tid & 3;

    float gA[DGc], gB[DGc];
    {
        const float* gp = g + ((((((size_t)b * Nc + i) * Nc + j0) * Sc + s) * Sc) + t) * DGc;
        float4 g0 = *reinterpret_cast<const float4*>(gp);
        float4 g1 = *reinterpret_cast<const float4*>(gp + 4);
        gA[0]=g0.x; gA[1]=g0.y; gA[2]=g0.z; gA[3]=g0.w;
        gA[4]=g1.x; gA[5]=g1.y; gA[6]=g1.z; gA[7]=g1.w;
        const float* gp2 = gp + (size_t)64 * Sc * Sc * DGc;
        float4 h0 = *reinterpret_cast<const float4*>(gp2);
        float4 h1 = *reinterpret_cast<const float4*>(gp2 + 4);
        gB[0]=h0.x; gB[1]=h0.y; gB[2]=h0.z; gB[3]=h0.w;
        gB[4]=h1.x; gB[5]=h1.y; gB[6]=h1.z; gB[7]=h1.w;
    }
    float fkA[CINc], fkB[CINc];
    {
        float4 v = *reinterpret_cast<const float4*>(f + ((size_t)b * 512 + tid) * CINc);
        fkA[0]=v.x; fkA[1]=v.y; fkA[2]=v.z; fkA[3]=v.w;
        float4 x = *reinterpret_cast<const float4*>(f + ((size_t)b * 512 + tid + 256) * CINc);
        fkB[0]=x.x; fkB[1]=x.y; fkB[2]=x.z; fkB[3]=x.w;
    }

    // ---- epilogue keys: kappa = 64w + 16T + gq (+8) ----
    int mks[8];
    #pragma unroll
    for (int T = 0; T < 4; ++T) {
        int kap = 64 * w + 16 * T + gq;
        mks[2*T]   = mask[(size_t)b * 512 + kap];
        mks[2*T+1] = mask[(size_t)b * 512 + kap + 8];
    }

    __syncthreads();

    const uint32_t hb = smem_u32(dsm);
    float num[CINc], den[CINc];

    #pragma unroll 1
    for (int c = 0; c < CINc; ++c) {
        float kk[8];
        #pragma unroll
        for (int q = 0; q < 8; ++q) kk[q] = 0.f;

        #pragma unroll 1
        for (int m = 0; m < 2; ++m) {
            // ===== layer 1 (scalar f32x2, output-packed pairs) =====
            u64 hpA[16], hpB[16];
            if (m == 0) {
                const float* w1 = sf + KYW1t + c * 64;
                const float* b1 = sf + KYB1 + c * 32;
                const u64 fqd  = pk2(fq[c], fq[c]);
                const u64 fkAd = pk2(fkA[c], fkA[c]);
                const u64 fkBd = pk2(fkB[c], fkB[c]);
                #pragma unroll
                for (int q = 0; q < 8; ++q) {
                    ulonglong2 w0 = *reinterpret_cast<const ulonglong2*>(w1 + 4*q);
                    ulonglong2 wq = *reinterpret_cast<const ulonglong2*>(w1 + 32 + 4*q);
                    ulonglong2 bv = *reinterpret_cast<const ulonglong2*>(b1 + 4*q);
                    u64 t0 = fma2(fqd, wq.x, bv.x);
                    u64 t1 = fma2(fqd, wq.y, bv.y);
                    hpA[2*q]   = fma2(fkAd, w0.x, t0);
                    hpA[2*q+1] = fma2(fkAd, w0.y, t1);
                    hpB[2*q]   = fma2(fkBd, w0.x, t0);
                    hpB[2*q+1] = fma2(fkBd, w0.y, t1);
                }
            } else {
                const float* w1 = sf + KGW1t + c * 256;
                const float* b1 = sf + KGB1 + c * 32;
                #pragma unroll
                for (int q = 0; q < 8; ++q) {
                    ulonglong2 bv = *reinterpret_cast<const ulonglong2*>(b1 + 4*q);
                    hpA[2*q] = bv.x; hpA[2*q+1] = bv.y;
                    hpB[2*q] = bv.x; hpB[2*q+1] = bv.y;
                }
                #pragma unroll
                for (int k = 0; k < DGc; ++k) {
                    const u64 gad = pk2(gA[k], gA[k]);
                    const u64 gbd = pk2(gB[k], gB[k]);
                    const float* wk = w1 + k * 32;
                    #pragma unroll
                    for (int q = 0; q < 8; ++q) {
                        ulonglong2 wv = *reinterpret_cast<const ulonglong2*>(wk + 4*q);
                        hpA[2*q]   = fma2(gad, wv.x, hpA[2*q]);
                        hpA[2*q+1] = fma2(gad, wv.y, hpA[2*q+1]);
                        hpB[2*q]   = fma2(gbd, wv.x, hpB[2*q]);
                        hpB[2*q+1] = fma2(gbd, wv.y, hpB[2*q+1]);
                    }
                }
            }
            #pragma unroll
            for (int p = 0; p < 16; ++p) { hpA[p] = silu2p(hpA[p]); hpB[p] = silu2p(hpB[p]); }

            // ===== cvt to bf16 hi/lo and STS rows tid, tid+256 =====
            {
                uint32_t hi[16], lo[16];
                #pragma unroll
                for (int p = 0; p < 16; ++p) {
                    float e0, e1; upk2(hpA[p], e0, e1);
                    uint32_t h = cvt_bf2(e0, e1);
                    hi[p] = h;
                    lo[p] = cvt_bf2(e0 - bfl(h), e1 - bfh(h));
                }
                char* rp = dsm + tid * 144;
                #pragma unroll
                for (int q = 0; q < 4; ++q) {
                    *reinterpret_cast<uint4*>(rp + q * 16) =
                        make_uint4(hi[4*q], hi[4*q+1], hi[4*q+2], hi[4*q+3]);
                    *reinterpret_cast<uint4*>(rp + 64 + q * 16) =
                        make_uint4(lo[4*q], lo[4*q+1], lo[4*q+2], lo[4*q+3]);
                }
                #pragma unroll
                for (int p = 0; p < 16; ++p) {
                    float e0, e1; upk2(hpB[p], e0, e1);
                    uint32_t h = cvt_bf2(e0, e1);
                    hi[p] = h;
                    lo[p] = cvt_bf2(e0 - bfl(h), e1 - bfh(h));
                }
                rp = dsm + (tid + 256) * 144;
                #pragma unroll
                for (int q = 0; q < 4; ++q) {
                    *reinterpret_cast<uint4*>(rp + q * 16) =
                        make_uint4(hi[4*q], hi[4*q+1], hi[4*q+2], hi[4*q+3]);
                    *reinterpret_cast<uint4*>(rp + 64 + q * 16) =
                        make_uint4(lo[4*q], lo[4*q+1], lo[4*q+2], lo[4*q+3]);
                }
            }
            __syncthreads();

            // ===== B fragments: 8 conflict-free LDS.128 from pre-split smem =====
            uint32_t bfv[32];
            {
                const char* bp = dsm + BFR + (c * 2 + m) * 4096 + lane * 16;
                #pragma unroll
                for (int ch2 = 0; ch2 < 8; ++ch2) {
                    uint4 v = *reinterpret_cast<const uint4*>(bp + ch2 * 512);
                    bfv[ch2*4+0] = v.x; bfv[ch2*4+1] = v.y;
                    bfv[ch2*4+2] = v.z; bfv[ch2*4+3] = v.w;
                }
            }

            // ===== per-tile: ldmatrix A, 24 MMAs, epilogue =====
            const float* b2 = sf + (m ? KGB2 : KYB2) + c * HIDc;
            const float* w3 = sf + (m ? KGW3 : KYW3) + c * HIDc;
            const float  b3 = sf[(m ? KGB3 : KYB3) + c];
            const uint32_t lmbase = hb
                + (uint32_t)(64 * w + (lane & 7) + ((lane >> 3) & 1) * 8) * 144
                + ((lane >> 4) & 1) * 16;

            #pragma unroll 1
            for (int T = 0; T < 4; ++T) {
                uint32_t ahi[2][4], alo[2][4];
                const uint32_t ab = lmbase + (uint32_t)(16 * T) * 144;
                ldmx4(ahi[0], ab);
                ldmx4(ahi[1], ab + 32);
                ldmx4(alo[0], ab + 64);
                ldmx4(alo[1], ab + 96);

                float d[4][4];
                #pragma unroll
                for (int nt = 0; nt < 4; ++nt)
                    d[nt][0] = d[nt][1] = d[nt][2] = d[nt][3] = 0.f;

                #pragma unroll
                for (int q = 0; q < 2; ++q) {
                    #pragma unroll
                    for (int nt = 0; nt < 4; ++nt)
                        mma16816(d[nt], ahi[q], bfv[q*8+nt*2], bfv[q*8+nt*2+1]);
                    #pragma unroll
                    for (int nt = 0; nt < 4; ++nt)
                        mma16816(d[nt], alo[q], bfv[q*8+nt*2], bfv[q*8+nt*2+1]);
                    #pragma unroll
                    for (int nt = 0; nt < 4; ++nt)
                        mma16816(d[nt], ahi[q], bfv[16+q*8+nt*2], bfv[16+q*8+nt*2+1]);
                }

                // epilogue: rows gq, gq+8; cols nt*8 + (lane&3)*2, +1
                u64 t0 = pk2(0.f, 0.f), t1 = pk2(0.f, 0.f);
                const int co = (lane & 3) * 2;
                #pragma unroll
                for (int nt = 0; nt < 4; ++nt) {
                    u64 bb = *reinterpret_cast<const u64*>(b2 + nt * 8 + co);
                    u64 ww = *reinterpret_cast<const u64*>(w3 + nt * 8 + co);
                    t0 = fma2(silu2p(add2(pk2(d[nt][0], d[nt][1]), bb)), ww, t0);
                    t1 = fma2(silu2p(add2(pk2(d[nt][2], d[nt][3]), bb)), ww, t1);
                }
                float s0a, s0b, s1a, s1b;
                upk2(t0, s0a, s0b);
                upk2(t1, s1a, s1b);
                float s0 = s0a + s0b, s1 = s1a + s1b;
                s0 += __shfl_xor_sync(0xFFFFFFFFu, s0, 1);
                s0 += __shfl_xor_sync(0xFFFFFFFFu, s0, 2);
                s1 += __shfl_xor_sync(0xFFFFFFFFu, s1, 1);
                s1 += __shfl_xor_sync(0xFFFFFFFFu, s1, 2);
                kk[2*T]   += silu_fp(s0 + b3);
                kk[2*T+1] += silu_fp(s1 + b3);
            }
            __syncthreads();   // before next round overwrites h-buffer
        }

        // ===== exp + mask + num/den over this thread's 8 epilogue keys =====
        float nc = 0.f, dc = 0.f;
        #pragma unroll
        for (int T = 0; T < 4; ++T) {
            int kap = 64 * w + 16 * T + gq;
            float fk0 = f[((size_t)b * 512 + kap) * CINc + c];
            float fk1 = f[((size_t)b * 512 + kap + 8) * CINc + c];
            float e0 = mks[2*T]   ? ex2f(LOG2E * kk[2*T])   : 0.f;
            float e1 = mks[2*T+1] ? ex2f(LOG2E * kk[2*T+1]) : 0.f;
            dc += e0 + e1;
            nc += fmaf(e0, fk0, e1 * fk1);
        }
        num[c] = nc;
        den[c] = dc;
    }

    // ---- reduce over 256 threads (quad replication x4 cancels in n/d) ----
    #pragma unroll
    for (int c = 0; c < CINc; ++c) {
        #pragma unroll
        for (int off = 16; off > 0; off >>= 1) {
            num[c] += __shfl_xor_sync(0xFFFFFFFFu, num[c], off);
            den[c] += __shfl_xor_sync(0xFFFFFFFFu, den[c], off);
        }
    }
    if (lane == 0) {
        #pragma unroll
        for (int c = 0; c < CINc; ++c) {
            sf[SRED + w * 8 + c]     = num[c];
            sf[SRED + w * 8 + 4 + c] = den[c];
        }
    }
    __syncthreads();

    if (tid < COUTc) {
        const int o = tid;
        const float mq = (mask[((size_t)b * Nc + i) * Sc + s] != 0) ? 1.0f : 0.0f;
        float acc = 0.0f;
        #pragma unroll
        for (int c = 0; c < CINc; ++c) {
            float n = 0.0f, d = 0.0f;
            #pragma unroll
            for (int ww = 0; ww < 8; ++ww) {
                n += sf[SRED + ww * 8 + c];
                d += sf[SRED + ww * 8 + 4 + c];
            }
            const float cf = (fq[c] + n / d) * mq;
            acc = fmaf(cf, sf[WOUT + o * CINc + c], acc);
        }
        out[(((size_t)b * Nc + i) * Sc + s) * COUTc + o] = acc;
    }
}

extern "C" void kernel_launch(void* const* d_in, const int* in_sizes, int n_in,
                              void* d_out, int out_size)
{
    const float* g    = (const float*)d_in[0];
    const float* f    = (const float*)d_in[1];
    const int*   mask = (const int*)d_in[2];
    const float* kyW1 = (const float*)d_in[3];
    const float* kyb1 = (const float*)d_in[4];
    const float* kyW2 = (const float*)d_in[5];
    const float* kyb2 = (const float*)d_in[6];
    const float* kyW3 = (const float*)d_in[7];
    const float* kyb3 = (const float*)d_in[8];
    const float* kgW1 = (const float*)d_in[9];
    const float* kgb1 = (const float*)d_in[10];
    const float* kgW2 = (const float*)d_in[11];
    const float* kgb2 = (const float*)d_in[12];
    const float* kgW3 = (const float*)d_in[13];
    const float* kgb3 = (const float*)d_in[14];
    const float* wout = (const float*)d_in[15];
    float* out = (float*)d_out;

    cudaFuncSetAttribute(ema_kernel, cudaFuncAttributeMaxDynamicSharedMemorySize, SMEM_BYTES);
    ema_kernel<<<Bc * Nc * Sc, 256, SMEM_BYTES>>>(g, f, mask,
                                      kyW1, kyb1, kyW2, kyb2, kyW3, kyb3,
                                      kgW1, kgb1, kgW2, kgb2, kgW3, kgb3,
                                      wout, out);
}

// round 15
// speedup vs baseline: 1.5003x; 1.1284x over previous
#include <cuda_runtime.h>
#include <cuda_bf16.h>
#include <cstdint>

#define Bc    2
#define Nc    128
#define Sc    4
#define DGc   8
#define CINc  4
#define COUTc 8
#define HIDc  32

// Dynamic smem:
// [0, 73728): h-buffer, 512 rows x 144B stride (hi bf16 [0,64), lo bf16 [64,128), pad).
//   Warp w owns rows [64w, 64w+64) exclusively (write in layer-1, read in ldmatrix)
//   -> only __syncwarp() needed in the hot loop.
// [73728, 106496): pre-split B fragments: 8 rounds x 4KB (conflict-free LDS.128).
// floats at +106496: layer-1 weights (input-major, x0.5), biases/w3 (x0.5), wout.
#define HBUF_BYTES 73728
#define BFR 73728
#define SFOFF 106496
#define KYW1t 0        // [c][k2][o]  256
#define KGW1t 256      // [c][k8][o]  1024
#define KYB1  1280     // 128
#define KGB1  1408     // 128
#define KYB2  1536     // 128 (x0.5)
#define KGB2  1664     // 128
#define KYW3  1792     // 128 (x0.5)
#define KGW3  1920     // 128
#define KYB3  2048     // 4
#define KGB3  2052     // 4
#define WOUT  2056     // 32
#define SRED  2088     // 64
#define SF_FLOATS 2152
#define SMEM_BYTES (SFOFF + SF_FLOATS * 4)

typedef unsigned long long u64;

__device__ __forceinline__ u64 pk2(float lo, float hi) {
    u64 r; asm("mov.b64 %0, {%1, %2};" : "=l"(r) : "f"(lo), "f"(hi)); return r;
}
__device__ __forceinline__ void upk2(u64 v, float& lo, float& hi) {
    asm("mov.b64 {%0, %1}, %2;" : "=f"(lo), "=f"(hi) : "l"(v));
}
__device__ __forceinline__ u64 fma2(u64 a, u64 b, u64 c) {
    u64 d; asm("fma.rn.f32x2 %0, %1, %2, %3;" : "=l"(d) : "l"(a), "l"(b), "l"(c)); return d;
}
__device__ __forceinline__ u64 add2(u64 a, u64 b) {
    u64 d; asm("add.rn.f32x2 %0, %1, %2;" : "=l"(d) : "l"(a), "l"(b)); return d;
}
__device__ __forceinline__ float ex2f(float x) {
    float r; asm("ex2.approx.f32 %0, %1;" : "=f"(r) : "f"(x)); return r;
}
__device__ __forceinline__ float tanhf_a(float x) {
    float r; asm("tanh.approx.f32 %0, %1;" : "=f"(r) : "f"(x)); return r;
}

#define LOG2E 1.4426950408889634f

__device__ __forceinline__ u64 silu2p(u64 acc) {   // acc = x/2 -> silu(x)
    float a, b; upk2(acc, a, b);
    return fma2(acc, pk2(tanhf_a(a), tanhf_a(b)), acc);
}
__device__ __forceinline__ float silu_fp(float acc) {
    return fmaf(acc, tanhf_a(acc), acc);
}

__device__ __forceinline__ uint32_t cvt_bf2(float lo, float hi) {
    uint32_t r; asm("cvt.rn.bf16x2.f32 %0, %1, %2;" : "=r"(r) : "f"(hi), "f"(lo)); return r;
}
__device__ __forceinline__ float bfl(uint32_t h) { return __uint_as_float(h << 16); }
__device__ __forceinline__ float bfh(uint32_t h) { return __uint_as_float(h & 0xFFFF0000u); }

__device__ __forceinline__ uint32_t smem_u32(const void* p) {
    uint32_t a;
    asm("{ .reg .u64 t; cvta.to.shared.u64 t, %1; cvt.u32.u64 %0, t; }" : "=r"(a) : "l"(p));
    return a;
}

__device__ __forceinline__ void ldmx4(uint32_t* r, uint32_t addr) {
    asm volatile("ldmatrix.sync.aligned.m8n8.x4.shared.b16 {%0,%1,%2,%3}, [%4];"
                 : "=r"(r[0]), "=r"(r[1]), "=r"(r[2]), "=r"(r[3]) : "r"(addr));
}

__device__ __forceinline__ void mma16816(float* d, const uint32_t* a,
                                         uint32_t b0, uint32_t b1) {
    asm volatile("mma.sync.aligned.m16n8k16.row.col.f32.bf16.bf16.f32 "
                 "{%0,%1,%2,%3}, {%4,%5,%6,%7}, {%8,%9}, {%0,%1,%2,%3};"
                 : "+f"(d[0]), "+f"(d[1]), "+f"(d[2]), "+f"(d[3])
                 : "r"(a[0]), "r"(a[1]), "r"(a[2]), "r"(a[3]), "r"(b0), "r"(b1));
}

__global__ __launch_bounds__(256, 2)
void ema_kernel(const float* __restrict__ g,
                const float* __restrict__ f,
                const int* __restrict__ mask,
                const float* __restrict__ kyW1, const float* __restrict__ kyb1,
                const float* __restrict__ kyW2, const float* __restrict__ kyb2,
                const float* __restrict__ kyW3, const float* __restrict__ kyb3,
                const float* __restrict__ kgW1, const float* __restrict__ kgb1,
                const float* __restrict__ kgW2, const float* __restrict__ kgb2,
                const float* __restrict__ kgW3, const float* __restrict__ kgb3,
                const float* __restrict__ wout,
                float* __restrict__ out)
{
    extern __shared__ __align__(16) char dsm[];
    float* sf = reinterpret_cast<float*>(dsm + SFOFF);

    const int tid  = threadIdx.x;
    const int w    = tid >> 5;
    const int lane = tid & 31;
    const int gq   = lane >> 2;

    // ---- stage layer-1 weights / biases / w3 (all x0.5, input-major) ----
    for (int idx = tid; idx < 1024; idx += 256) {
        int c = idx >> 8, o = (idx >> 3) & 31, k = idx & 7;
        sf[KGW1t + c * 256 + k * 32 + o] = 0.5f * kgW1[idx];
    }
    {
        int c = tid >> 6, o = (tid >> 1) & 31, k = tid & 1;
        sf[KYW1t + c * 64 + k * 32 + o] = 0.5f * kyW1[tid];
    }
    for (int idx = tid; idx < 128; idx += 256) {
        sf[KYB1 + idx] = 0.5f * kyb1[idx];
        sf[KGB1 + idx] = 0.5f * kgb1[idx];
        sf[KYB2 + idx] = 0.5f * kyb2[idx];
        sf[KGB2 + idx] = 0.5f * kgb2[idx];
        sf[KYW3 + idx] = 0.5f * kyW3[idx];
        sf[KGW3 + idx] = 0.5f * kgW3[idx];
    }
    if (tid < 4) { sf[KYB3 + tid] = 0.5f * kyb3[tid]; sf[KGB3 + tid] = 0.5f * kgb3[tid]; }
    if (tid < 32) sf[WOUT + tid] = wout[tid];

    // ---- stage pre-split B fragments ----
    for (int idx = tid; idx < 4096; idx += 256) {
        int r  = idx >> 9, rem2 = idx & 511, ln = rem2 >> 4, jj = rem2 & 15;
        int cc = r >> 1,  mm  = r & 1;
        int q  = jj >> 3, nt  = (jj >> 1) & 3, pr = jj & 1;
        const float* W2 = (mm ? kgW2 : kyW2) + cc * 1024;
        int o = nt * 8 + (ln >> 2);
        int k = q * 16 + pr * 8 + (ln & 3) * 2;
        float v0 = 0.5f * W2[o * 32 + k];
        float v1 = 0.5f * W2[o * 32 + k + 1];
        uint32_t hi = cvt_bf2(v0, v1);
        uint32_t lo = cvt_bf2(v0 - bfl(hi), v1 - bfh(hi));
        char* base = dsm + BFR + r * 4096 + ln * 16 + (jj & 3) * 4;
        *reinterpret_cast<uint32_t*>(base + (jj >> 2) * 512)       = hi;
        *reinterpret_cast<uint32_t*>(base + ((jj >> 2) + 4) * 512) = lo;
    }

    // ---- decode query (b, i, s) ----
    const int bid = blockIdx.x;
    const int b   = bid >> 9;
    const int rem = bid & 511;
    const int i   = rem >> 2;
    const int s   = rem & 3;

    float fq[CINc];
    {
        float4 v = *reinterpret_cast<const float4*>(f + (((size_t)b * Nc + i) * Sc + s) * CINc);
        fq[0] = v.x; fq[1] = v.y; fq[2] = v.z; fq[3] = v.w;
    }

    // ---- layer-1 keys owned by this thread: kapA = 64w+lane, kapB = kapA+32 ----
    const int kapA = 64 * w + lane;
    const int kapB = kapA + 32;
    const int jA = kapA >> 2;          // jB = jA + 8, same t
    const int t  = kapA & 3;

    float gA[DGc], gB[DGc];
    {
        const float* gp = g + ((((((size_t)b * Nc + i) * Nc + jA) * Sc + s) * Sc) + t) * DGc;
        float4 g0 = *reinterpret_cast<const float4*>(gp);
        float4 g1 = *reinterpret_cast<const float4*>(gp + 4);
        gA[0]=g0.x; gA[1]=g0.y; gA[2]=g0.z; gA[3]=g0.w;
        gA[4]=g1.x; gA[5]=g1.y; gA[6]=g1.z; gA[7]=g1.w;
        const float* gp2 = gp + (size_t)8 * Sc * Sc * DGc;   // j + 8
        float4 h0 = *reinterpret_cast<const float4*>(gp2);
        float4 h1 = *reinterpret_cast<const float4*>(gp2 + 4);
        gB[0]=h0.x; gB[1]=h0.y; gB[2]=h0.z; gB[3]=h0.w;
        gB[4]=h1.x; gB[5]=h1.y; gB[6]=h1.z; gB[7]=h1.w;
    }
    float fkA[CINc], fkB[CINc];
    {
        float4 v = *reinterpret_cast<const float4*>(f + ((size_t)b * 512 + kapA) * CINc);
        fkA[0]=v.x; fkA[1]=v.y; fkA[2]=v.z; fkA[3]=v.w;
        float4 x = *reinterpret_cast<const float4*>(f + ((size_t)b * 512 + kapB) * CINc);
        fkB[0]=x.x; fkB[1]=x.y; fkB[2]=x.z; fkB[3]=x.w;
    }

    // ---- epilogue keys: kappa = 64w + 16T + gq (+8) ----
    int mks[8];
    #pragma unroll
    for (int T = 0; T < 4; ++T) {
        int kap = 64 * w + 16 * T + gq;
        mks[2*T]   = mask[(size_t)b * 512 + kap];
        mks[2*T+1] = mask[(size_t)b * 512 + kap + 8];
    }

    __syncthreads();   // staging complete (cross-warp); hot loop is warp-local

    const uint32_t hb = smem_u32(dsm);
    float num[CINc], den[CINc];

    #pragma unroll 1
    for (int c = 0; c < CINc; ++c) {
        float kk[8];
        #pragma unroll
        for (int q = 0; q < 8; ++q) kk[q] = 0.f;

        #pragma unroll 1
        for (int m = 0; m < 2; ++m) {
            // ===== layer 1 (scalar f32x2, output-packed pairs) =====
            u64 hpA[16], hpB[16];
            if (m == 0) {
                const float* w1 = sf + KYW1t + c * 64;
                const float* b1 = sf + KYB1 + c * 32;
                const u64 fqd  = pk2(fq[c], fq[c]);
                const u64 fkAd = pk2(fkA[c], fkA[c]);
                const u64 fkBd = pk2(fkB[c], fkB[c]);
                #pragma unroll
                for (int q = 0; q < 8; ++q) {
                    ulonglong2 w0 = *reinterpret_cast<const ulonglong2*>(w1 + 4*q);
                    ulonglong2 wq = *reinterpret_cast<const ulonglong2*>(w1 + 32 + 4*q);
                    ulonglong2 bv = *reinterpret_cast<const ulonglong2*>(b1 + 4*q);
                    u64 t0 = fma2(fqd, wq.x, bv.x);
                    u64 t1 = fma2(fqd, wq.y, bv.y);
                    hpA[2*q]   = fma2(fkAd, w0.x, t0);
                    hpA[2*q+1] = fma2(fkAd, w0.y, t1);
                    hpB[2*q]   = fma2(fkBd, w0.x, t0);
                    hpB[2*q+1] = fma2(fkBd, w0.y, t1);
                }
            } else {
                const float* w1 = sf + KGW1t + c * 256;
                const float* b1 = sf + KGB1 + c * 32;
                #pragma unroll
                for (int q = 0; q < 8; ++q) {
                    ulonglong2 bv = *reinterpret_cast<const ulonglong2*>(b1 + 4*q);
                    hpA[2*q] = bv.x; hpA[2*q+1] = bv.y;
                    hpB[2*q] = bv.x; hpB[2*q+1] = bv.y;
                }
                #pragma unroll
                for (int k = 0; k < DGc; ++k) {
                    const u64 gad = pk2(gA[k], gA[k]);
                    const u64 gbd = pk2(gB[k], gB[k]);
                    const float* wk = w1 + k * 32;
                    #pragma unroll
                    for (int q = 0; q < 8; ++q) {
                        ulonglong2 wv = *reinterpret_cast<const ulonglong2*>(wk + 4*q);
                        hpA[2*q]   = fma2(gad, wv.x, hpA[2*q]);
                        hpA[2*q+1] = fma2(gad, wv.y, hpA[2*q+1]);
                        hpB[2*q]   = fma2(gbd, wv.x, hpB[2*q]);
                        hpB[2*q+1] = fma2(gbd, wv.y, hpB[2*q+1]);
                    }
                }
            }
            #pragma unroll
            for (int p = 0; p < 16; ++p) { hpA[p] = silu2p(hpA[p]); hpB[p] = silu2p(hpB[p]); }

            // ===== cvt to bf16 hi/lo and STS rows kapA, kapB (warp-owned) =====
            {
                uint32_t hi[16], lo[16];
                #pragma unroll
                for (int p = 0; p < 16; ++p) {
                    float e0, e1; upk2(hpA[p], e0, e1);
                    uint32_t h = cvt_bf2(e0, e1);
                    hi[p] = h;
                    lo[p] = cvt_bf2(e0 - bfl(h), e1 - bfh(h));
                }
                char* rp = dsm + kapA * 144;
                #pragma unroll
                for (int q = 0; q < 4; ++q) {
                    *reinterpret_cast<uint4*>(rp + q * 16) =
                        make_uint4(hi[4*q], hi[4*q+1], hi[4*q+2], hi[4*q+3]);
                    *reinterpret_cast<uint4*>(rp + 64 + q * 16) =
                        make_uint4(lo[4*q], lo[4*q+1], lo[4*q+2], lo[4*q+3]);
                }
                #pragma unroll
                for (int p = 0; p < 16; ++p) {
                    float e0, e1; upk2(hpB[p], e0, e1);
                    uint32_t h = cvt_bf2(e0, e1);
                    hi[p] = h;
                    lo[p] = cvt_bf2(e0 - bfl(h), e1 - bfh(h));
                }
                rp = dsm + kapB * 144;
                #pragma unroll
                for (int q = 0; q < 4; ++q) {
                    *reinterpret_cast<uint4*>(rp + q * 16) =
                        make_uint4(hi[4*q], hi[4*q+1], hi[4*q+2], hi[4*q+3]);
                    *reinterpret_cast<uint4*>(rp + 64 + q * 16) =
                        make_uint4(lo[4*q], lo[4*q+1], lo[4*q+2], lo[4*q+3]);
                }
            }
            __syncwarp();

            // ===== B fragments: 8 conflict-free LDS.128 =====
            uint32_t bfv[32];
            {
                const char* bp = dsm + BFR + (c * 2 + m) * 4096 + lane * 16;
                #pragma unroll
                for (int ch2 = 0; ch2 < 8; ++ch2) {
                    uint4 v = *reinterpret_cast<const uint4*>(bp + ch2 * 512);
                    bfv[ch2*4+0] = v.x; bfv[ch2*4+1] = v.y;
                    bfv[ch2*4+2] = v.z; bfv[ch2*4+3] = v.w;
                }
            }

            // ===== per-tile: ldmatrix A, 24 MMAs, epilogue =====
            const float* b2 = sf + (m ? KGB2 : KYB2) + c * HIDc;
            const float* w3 = sf + (m ? KGW3 : KYW3) + c * HIDc;
            const float  b3 = sf[(m ? KGB3 : KYB3) + c];
            const uint32_t lmbase = hb
                + (uint32_t)(64 * w + (lane & 7) + ((lane >> 3) & 1) * 8) * 144
                + ((lane >> 4) & 1) * 16;

            #pragma unroll 1
            for (int T = 0; T < 4; ++T) {
                uint32_t ahi[2][4], alo[2][4];
                const uint32_t ab = lmbase + (uint32_t)(16 * T) * 144;
                ldmx4(ahi[0], ab);
                ldmx4(ahi[1], ab + 32);
                ldmx4(alo[0], ab + 64);
                ldmx4(alo[1], ab + 96);

                float d[4][4];
                #pragma unroll
                for (int nt = 0; nt < 4; ++nt)
                    d[nt][0] = d[nt][1] = d[nt][2] = d[nt][3] = 0.f;

                #pragma unroll
                for (int q = 0; q < 2; ++q) {
                    #pragma unroll
                    for (int nt = 0; nt < 4; ++nt)
                        mma16816(d[nt], ahi[q], bfv[q*8+nt*2], bfv[q*8+nt*2+1]);
                    #pragma unroll
                    for (int nt = 0; nt < 4; ++nt)
                        mma16816(d[nt], alo[q], bfv[q*8+nt*2], bfv[q*8+nt*2+1]);
                    #pragma unroll
                    for (int nt = 0; nt < 4; ++nt)
                        mma16816(d[nt], ahi[q], bfv[16+q*8+nt*2], bfv[16+q*8+nt*2+1]);
                }

                // epilogue: rows gq, gq+8; cols nt*8 + (lane&3)*2, +1
                u64 t0 = pk2(0.f, 0.f), t1 = pk2(0.f, 0.f);
                const int co = (lane & 3) * 2;
                #pragma unroll
                for (int nt = 0; nt < 4; ++nt) {
                    u64 bb = *reinterpret_cast<const u64*>(b2 + nt * 8 + co);
                    u64 ww = *reinterpret_cast<const u64*>(w3 + nt * 8 + co);
                    t0 = fma2(silu2p(add2(pk2(d[nt][0], d[nt][1]), bb)), ww, t0);
                    t1 = fma2(silu2p(add2(pk2(d[nt][2], d[nt][3]), bb)), ww, t1);
                }
                float s0a, s0b, s1a, s1b;
                upk2(t0, s0a, s0b);
                upk2(t1, s1a, s1b);
                float s0 = s0a + s0b, s1 = s1a + s1b;
                s0 += __shfl_xor_sync(0xFFFFFFFFu, s0, 1);
                s0 += __shfl_xor_sync(0xFFFFFFFFu, s0, 2);
                s1 += __shfl_xor_sync(0xFFFFFFFFu, s1, 1);
                s1 += __shfl_xor_sync(0xFFFFFFFFu, s1, 2);
                kk[2*T]   += silu_fp(s0 + b3);
                kk[2*T+1] += silu_fp(s1 + b3);
            }
            __syncwarp();   // before next round overwrites this warp's h rows
        }

        // ===== exp + mask + num/den over this thread's 8 epilogue keys =====
        float nc = 0.f, dc = 0.f;
        #pragma unroll
        for (int T = 0; T < 4; ++T) {
            int kap = 64 * w + 16 * T + gq;
            float fk0 = f[((size_t)b * 512 + kap) * CINc + c];
            float fk1 = f[((size_t)b * 512 + kap + 8) * CINc + c];
            float e0 = mks[2*T]   ? ex2f(LOG2E * kk[2*T])   : 0.f;
            float e1 = mks[2*T+1] ? ex2f(LOG2E * kk[2*T+1]) : 0.f;
            dc += e0 + e1;
            nc += fmaf(e0, fk0, e1 * fk1);
        }
        num[c] = nc;
        den[c] = dc;
    }

    // ---- reduce over 256 threads (quad replication x4 cancels in n/d) ----
    #pragma unroll
    for (int c = 0; c < CINc; ++c) {
        #pragma unroll
        for (int off = 16; off > 0; off >>= 1) {
            num[c] += __shfl_xor_sync(0xFFFFFFFFu, num[c], off);
            den[c] += __shfl_xor_sync(0xFFFFFFFFu, den[c], off);
        }
    }
    if (lane == 0) {
        #pragma unroll
        for (int c = 0; c < CINc; ++c) {
            sf[SRED + w * 8 + c]     = num[c];
            sf[SRED + w * 8 + 4 + c] = den[c];
        }
    }
    __syncthreads();

    if (tid < COUTc) {
        const int o = tid;
        const float mq = (mask[((size_t)b * Nc + i) * Sc + s] != 0) ? 1.0f : 0.0f;
        float acc = 0.0f;
        #pragma unroll
        for (int c = 0; c < CINc; ++c) {
            float n = 0.0f, d = 0.0f;
            #pragma unroll
            for (int ww = 0; ww < 8; ++ww) {
                n += sf[SRED + ww * 8 + c];
                d += sf[SRED + ww * 8 + 4 + c];
            }
            const float cf = (fq[c] + n / d) * mq;
            acc = fmaf(cf, sf[WOUT + o * CINc + c], acc);
        }
        out[(((size_t)b * Nc + i) * Sc + s) * COUTc + o] = acc;
    }
}

extern "C" void kernel_launch(void* const* d_in, const int* in_sizes, int n_in,
                              void* d_out, int out_size)
{
    const float* g    = (const float*)d_in[0];
    const float* f    = (const float*)d_in[1];
    const int*   mask = (const int*)d_in[2];
    const float* kyW1 = (const float*)d_in[3];
    const float* kyb1 = (const float*)d_in[4];
    const float* kyW2 = (const float*)d_in[5];
    const float* kyb2 = (const float*)d_in[6];
    const float* kyW3 = (const float*)d_in[7];
    const float* kyb3 = (const float*)d_in[8];
    const float* kgW1 = (const float*)d_in[9];
    const float* kgb1 = (const float*)d_in[10];
    const float* kgW2 = (const float*)d_in[11];
    const float* kgb2 = (const float*)d_in[12];
    const float* kgW3 = (const float*)d_in[13];
    const float* kgb3 = (const float*)d_in[14];
    const float* wout = (const float*)d_in[15];
    float* out = (float*)d_out;

    cudaFuncSetAttribute(ema_kernel, cudaFuncAttributeMaxDynamicSharedMemorySize, SMEM_BYTES);
    ema_kernel<<<Bc * Nc * Sc, 256, SMEM_BYTES>>>(g, f, mask,
                                      kyW1, kyb1, kyW2, kyb2, kyW3, kyb3,
                                      kgW1, kgb1, kgW2, kgb2, kgW3, kgb3,
                                      wout, out);
}

// round 16
// speedup vs baseline: 1.5741x; 1.0492x over previous
#include <cuda_runtime.h>
#include <cuda_bf16.h>
#include <cstdint>

#define Bc    2
#define Nc    128
#define Sc    4
#define DGc   8
#define CINc  4
#define COUTc 8
#define HIDc  32

// Dynamic smem:
// [0, 73728): h-buffer, 512 rows x 144B stride (hi bf16 [0,64), lo bf16 [64,128), pad).
//   Warp w owns rows [64w, 64w+64) exclusively -> only __syncwarp() in hot loop.
// [73728, 106496): pre-split B fragments: 8 rounds x 4KB (conflict-free LDS.128).
// floats at +106496: layer-1 weights (input-major, x0.5), biases/w3 (x0.5), wout.
#define HBUF_BYTES 73728
#define BFR 73728
#define SFOFF 106496
#define KYW1t 0        // [c][k2][o]  256
#define KGW1t 256      // [c][k8][o]  1024
#define KYB1  1280     // 128
#define KGB1  1408     // 128
#define KYB2  1536     // 128 (x0.5)
#define KGB2  1664     // 128
#define KYW3  1792     // 128 (x0.5)
#define KGW3  1920     // 128
#define KYB3  2048     // 4
#define KGB3  2052     // 4
#define WOUT  2056     // 32
#define SRED  2088     // 64
#define SF_FLOATS 2152
#define SMEM_BYTES (SFOFF + SF_FLOATS * 4)

typedef unsigned long long u64;

__device__ __forceinline__ u64 pk2(float lo, float hi) {
    u64 r; asm("mov.b64 %0, {%1, %2};" : "=l"(r) : "f"(lo), "f"(hi)); return r;
}
__device__ __forceinline__ void upk2(u64 v, float& lo, float& hi) {
    asm("mov.b64 {%0, %1}, %2;" : "=f"(lo), "=f"(hi) : "l"(v));
}
__device__ __forceinline__ u64 fma2(u64 a, u64 b, u64 c) {
    u64 d; asm("fma.rn.f32x2 %0, %1, %2, %3;" : "=l"(d) : "l"(a), "l"(b), "l"(c)); return d;
}
__device__ __forceinline__ u64 add2(u64 a, u64 b) {
    u64 d; asm("add.rn.f32x2 %0, %1, %2;" : "=l"(d) : "l"(a), "l"(b)); return d;
}
__device__ __forceinline__ float ex2f(float x) {
    float r; asm("ex2.approx.f32 %0, %1;" : "=f"(r) : "f"(x)); return r;
}
__device__ __forceinline__ float tanhf_a(float x) {
    float r; asm("tanh.approx.f32 %0, %1;" : "=f"(r) : "f"(x)); return r;
}

#define LOG2E 1.4426950408889634f

__device__ __forceinline__ u64 silu2p(u64 acc) {   // acc = x/2 -> silu(x)
    float a, b; upk2(acc, a, b);
    return fma2(acc, pk2(tanhf_a(a), tanhf_a(b)), acc);
}
__device__ __forceinline__ float silu_fp(float acc) {
    return fmaf(acc, tanhf_a(acc), acc);
}

__device__ __forceinline__ uint32_t cvt_bf2(float lo, float hi) {
    uint32_t r; asm("cvt.rn.bf16x2.f32 %0, %1, %2;" : "=r"(r) : "f"(hi), "f"(lo)); return r;
}
__device__ __forceinline__ float bfl(uint32_t h) { return __uint_as_float(h << 16); }
__device__ __forceinline__ float bfh(uint32_t h) { return __uint_as_float(h & 0xFFFF0000u); }

__device__ __forceinline__ uint32_t smem_u32(const void* p) {
    uint32_t a;
    asm("{ .reg .u64 t; cvta.to.shared.u64 t, %1; cvt.u32.u64 %0, t; }" : "=r"(a) : "l"(p));
    return a;
}

__device__ __forceinline__ void ldmx4(uint32_t* r, uint32_t addr) {
    asm volatile("ldmatrix.sync.aligned.m8n8.x4.shared.b16 {%0,%1,%2,%3}, [%4];"
                 : "=r"(r[0]), "=r"(r[1]), "=r"(r[2]), "=r"(r[3]) : "r"(addr));
}

__device__ __forceinline__ void mma16816(float* d, const uint32_t* a,
                                         uint32_t b0, uint32_t b1) {
    asm volatile("mma.sync.aligned.m16n8k16.row.col.f32.bf16.bf16.f32 "
                 "{%0,%1,%2,%3}, {%4,%5,%6,%7}, {%8,%9}, {%0,%1,%2,%3};"
                 : "+f"(d[0]), "+f"(d[1]), "+f"(d[2]), "+f"(d[3])
                 : "r"(a[0]), "r"(a[1]), "r"(a[2]), "r"(a[3]), "r"(b0), "r"(b1));
}

__global__ __launch_bounds__(256, 2)
void ema_kernel(const float* __restrict__ g,
                const float* __restrict__ f,
                const int* __restrict__ mask,
                const float* __restrict__ kyW1, const float* __restrict__ kyb1,
                const float* __restrict__ kyW2, const float* __restrict__ kyb2,
                const float* __restrict__ kyW3, const float* __restrict__ kyb3,
                const float* __restrict__ kgW1, const float* __restrict__ kgb1,
                const float* __restrict__ kgW2, const float* __restrict__ kgb2,
                const float* __restrict__ kgW3, const float* __restrict__ kgb3,
                const float* __restrict__ wout,
                float* __restrict__ out)
{
    extern __shared__ __align__(16) char dsm[];
    float* sf = reinterpret_cast<float*>(dsm + SFOFF);

    const int tid  = threadIdx.x;
    const int w    = tid >> 5;
    const int lane = tid & 31;
    const int gq   = lane >> 2;

    // ---- stage layer-1 weights / biases / w3 (all x0.5, input-major) ----
    for (int idx = tid; idx < 1024; idx += 256) {
        int c = idx >> 8, o = (idx >> 3) & 31, k = idx & 7;
        sf[KGW1t + c * 256 + k * 32 + o] = 0.5f * kgW1[idx];
    }
    {
        int c = tid >> 6, o = (tid >> 1) & 31, k = tid & 1;
        sf[KYW1t + c * 64 + k * 32 + o] = 0.5f * kyW1[tid];
    }
    for (int idx = tid; idx < 128; idx += 256) {
        sf[KYB1 + idx] = 0.5f * kyb1[idx];
        sf[KGB1 + idx] = 0.5f * kgb1[idx];
        sf[KYB2 + idx] = 0.5f * kyb2[idx];
        sf[KGB2 + idx] = 0.5f * kgb2[idx];
        sf[KYW3 + idx] = 0.5f * kyW3[idx];
        sf[KGW3 + idx] = 0.5f * kgW3[idx];
    }
    if (tid < 4) { sf[KYB3 + tid] = 0.5f * kyb3[tid]; sf[KGB3 + tid] = 0.5f * kgb3[tid]; }
    if (tid < 32) sf[WOUT + tid] = wout[tid];

    // ---- stage pre-split B fragments ----
    for (int idx = tid; idx < 4096; idx += 256) {
        int r  = idx >> 9, rem2 = idx & 511, ln = rem2 >> 4, jj = rem2 & 15;
        int cc = r >> 1,  mm  = r & 1;
        int q  = jj >> 3, nt  = (jj >> 1) & 3, pr = jj & 1;
        const float* W2 = (mm ? kgW2 : kyW2) + cc * 1024;
        int o = nt * 8 + (ln >> 2);
        int k = q * 16 + pr * 8 + (ln & 3) * 2;
        float v0 = 0.5f * W2[o * 32 + k];
        float v1 = 0.5f * W2[o * 32 + k + 1];
        uint32_t hi = cvt_bf2(v0, v1);
        uint32_t lo = cvt_bf2(v0 - bfl(hi), v1 - bfh(hi));
        char* base = dsm + BFR + r * 4096 + ln * 16 + (jj & 3) * 4;
        *reinterpret_cast<uint32_t*>(base + (jj >> 2) * 512)       = hi;
        *reinterpret_cast<uint32_t*>(base + ((jj >> 2) + 4) * 512) = lo;
    }

    // ---- decode query (b, i, s) ----
    const int bid = blockIdx.x;
    const int b   = bid >> 9;
    const int rem = bid & 511;
    const int i   = rem >> 2;
    const int s   = rem & 3;

    float fq[CINc];
    {
        float4 v = *reinterpret_cast<const float4*>(f + (((size_t)b * Nc + i) * Sc + s) * CINc);
        fq[0] = v.x; fq[1] = v.y; fq[2] = v.z; fq[3] = v.w;
    }

    // ---- layer-1 keys: kapA = 64w+lane, kapB = kapA+32 ----
    const int kapA = 64 * w + lane;
    const int kapB = kapA + 32;
    const int jA = kapA >> 2;          // jB = jA + 8, same t
    const int t  = kapA & 3;

    float gA[DGc], gB[DGc];
    {
        const float* gp = g + ((((((size_t)b * Nc + i) * Nc + jA) * Sc + s) * Sc) + t) * DGc;
        float4 g0 = *reinterpret_cast<const float4*>(gp);
        float4 g1 = *reinterpret_cast<const float4*>(gp + 4);
        gA[0]=g0.x; gA[1]=g0.y; gA[2]=g0.z; gA[3]=g0.w;
        gA[4]=g1.x; gA[5]=g1.y; gA[6]=g1.z; gA[7]=g1.w;
        const float* gp2 = gp + (size_t)8 * Sc * Sc * DGc;   // j + 8
        float4 h0 = *reinterpret_cast<const float4*>(gp2);
        float4 h1 = *reinterpret_cast<const float4*>(gp2 + 4);
        gB[0]=h0.x; gB[1]=h0.y; gB[2]=h0.z; gB[3]=h0.w;
        gB[4]=h1.x; gB[5]=h1.y; gB[6]=h1.z; gB[7]=h1.w;
    }
    float fkA[CINc], fkB[CINc];
    {
        float4 v = *reinterpret_cast<const float4*>(f + ((size_t)b * 512 + kapA) * CINc);
        fkA[0]=v.x; fkA[1]=v.y; fkA[2]=v.z; fkA[3]=v.w;
        float4 x = *reinterpret_cast<const float4*>(f + ((size_t)b * 512 + kapB) * CINc);
        fkB[0]=x.x; fkB[1]=x.y; fkB[2]=x.z; fkB[3]=x.w;
    }

    // ---- epilogue keys: kappa = 64w + 16T + gq (+8) ----
    int mks[8];
    #pragma unroll
    for (int T = 0; T < 4; ++T) {
        int kap = 64 * w + 16 * T + gq;
        mks[2*T]   = mask[(size_t)b * 512 + kap];
        mks[2*T+1] = mask[(size_t)b * 512 + kap + 8];
    }

    __syncthreads();   // staging complete; hot loop is warp-local

    const uint32_t hb = smem_u32(dsm);
    float num[CINc], den[CINc];

    #pragma unroll 1
    for (int c = 0; c < CINc; ++c) {
        float kk[8];
        #pragma unroll
        for (int q = 0; q < 8; ++q) kk[q] = 0.f;

        #pragma unroll     // <- unrolled: m=1 layer-1 overlaps m=0 MMA/epilogue
        for (int m = 0; m < 2; ++m) {
            // ===== B fragments first (only depends on c,m): hide LDS latency =====
            uint32_t bfv[32];
            {
                const char* bp = dsm + BFR + (c * 2 + m) * 4096 + lane * 16;
                #pragma unroll
                for (int ch2 = 0; ch2 < 8; ++ch2) {
                    uint4 v = *reinterpret_cast<const uint4*>(bp + ch2 * 512);
                    bfv[ch2*4+0] = v.x; bfv[ch2*4+1] = v.y;
                    bfv[ch2*4+2] = v.z; bfv[ch2*4+3] = v.w;
                }
            }

            // ===== layer 1 (scalar f32x2, output-packed pairs) =====
            u64 hpA[16], hpB[16];
            if (m == 0) {
                const float* w1 = sf + KYW1t + c * 64;
                const float* b1 = sf + KYB1 + c * 32;
                const u64 fqd  = pk2(fq[c], fq[c]);
                const u64 fkAd = pk2(fkA[c], fkA[c]);
                const u64 fkBd = pk2(fkB[c], fkB[c]);
                #pragma unroll
                for (int q = 0; q < 8; ++q) {
                    ulonglong2 w0 = *reinterpret_cast<const ulonglong2*>(w1 + 4*q);
                    ulonglong2 wq = *reinterpret_cast<const ulonglong2*>(w1 + 32 + 4*q);
                    ulonglong2 bv = *reinterpret_cast<const ulonglong2*>(b1 + 4*q);
                    u64 t0 = fma2(fqd, wq.x, bv.x);
                    u64 t1 = fma2(fqd, wq.y, bv.y);
                    hpA[2*q]   = fma2(fkAd, w0.x, t0);
                    hpA[2*q+1] = fma2(fkAd, w0.y, t1);
                    hpB[2*q]   = fma2(fkBd, w0.x, t0);
                    hpB[2*q+1] = fma2(fkBd, w0.y, t1);
                }
            } else {
                const float* w1 = sf + KGW1t + c * 256;
                const float* b1 = sf + KGB1 + c * 32;
                #pragma unroll
                for (int q = 0; q < 8; ++q) {
                    ulonglong2 bv = *reinterpret_cast<const ulonglong2*>(b1 + 4*q);
                    hpA[2*q] = bv.x; hpA[2*q+1] = bv.y;
                    hpB[2*q] = bv.x; hpB[2*q+1] = bv.y;
                }
                #pragma unroll
                for (int k = 0; k < DGc; ++k) {
                    const u64 gad = pk2(gA[k], gA[k]);
                    const u64 gbd = pk2(gB[k], gB[k]);
                    const float* wk = w1 + k * 32;
                    #pragma unroll
                    for (int q = 0; q < 8; ++q) {
                        ulonglong2 wv = *reinterpret_cast<const ulonglong2*>(wk + 4*q);
                        hpA[2*q]   = fma2(gad, wv.x, hpA[2*q]);
                        hpA[2*q+1] = fma2(gad, wv.y, hpA[2*q+1]);
                        hpB[2*q]   = fma2(gbd, wv.x, hpB[2*q]);
                        hpB[2*q+1] = fma2(gbd, wv.y, hpB[2*q+1]);
                    }
                }
            }
            #pragma unroll
            for (int p = 0; p < 16; ++p) { hpA[p] = silu2p(hpA[p]); hpB[p] = silu2p(hpB[p]); }

            // ===== cvt to bf16 hi/lo and STS rows kapA, kapB (warp-owned) =====
            {
                uint32_t hi[16], lo[16];
                #pragma unroll
                for (int p = 0; p < 16; ++p) {
                    float e0, e1; upk2(hpA[p], e0, e1);
                    uint32_t h = cvt_bf2(e0, e1);
                    hi[p] = h;
                    lo[p] = cvt_bf2(e0 - bfl(h), e1 - bfh(h));
                }
                char* rp = dsm + kapA * 144;
                #pragma unroll
                for (int q = 0; q < 4; ++q) {
                    *reinterpret_cast<uint4*>(rp + q * 16) =
                        make_uint4(hi[4*q], hi[4*q+1], hi[4*q+2], hi[4*q+3]);
                    *reinterpret_cast<uint4*>(rp + 64 + q * 16) =
                        make_uint4(lo[4*q], lo[4*q+1], lo[4*q+2], lo[4*q+3]);
                }
                #pragma unroll
                for (int p = 0; p < 16; ++p) {
                    float e0, e1; upk2(hpB[p], e0, e1);
                    uint32_t h = cvt_bf2(e0, e1);
                    hi[p] = h;
                    lo[p] = cvt_bf2(e0 - bfl(h), e1 - bfh(h));
                }
                rp = dsm + kapB * 144;
                #pragma unroll
                for (int q = 0; q < 4; ++q) {
                    *reinterpret_cast<uint4*>(rp + q * 16) =
                        make_uint4(hi[4*q], hi[4*q+1], hi[4*q+2], hi[4*q+3]);
                    *reinterpret_cast<uint4*>(rp + 64 + q * 16) =
                        make_uint4(lo[4*q], lo[4*q+1], lo[4*q+2], lo[4*q+3]);
                }
            }
            __syncwarp();

            // ===== per-tile: ldmatrix A, 24 MMAs, epilogue =====
            const float* b2 = sf + (m ? KGB2 : KYB2) + c * HIDc;
            const float* w3 = sf + (m ? KGW3 : KYW3) + c * HIDc;
            const float  b3 = sf[(m ? KGB3 : KYB3) + c];
            const uint32_t lmbase = hb
                + (uint32_t)(64 * w + (lane & 7) + ((lane >> 3) & 1) * 8) * 144
                + ((lane >> 4) & 1) * 16;

            #pragma unroll 2   // <- 2-deep: tile t+1 ldmatrix/MMA overlaps tile t epilogue
            for (int T = 0; T < 4; ++T) {
                uint32_t ahi[2][4], alo[2][4];
                const uint32_t ab = lmbase + (uint32_t)(16 * T) * 144;
                ldmx4(ahi[0], ab);
                ldmx4(ahi[1], ab + 32);
                ldmx4(alo[0], ab + 64);
                ldmx4(alo[1], ab + 96);

                float d[4][4];
                #pragma unroll
                for (int nt = 0; nt < 4; ++nt)
                    d[nt][0] = d[nt][1] = d[nt][2] = d[nt][3] = 0.f;

                #pragma unroll
                for (int q = 0; q < 2; ++q) {
                    #pragma unroll
                    for (int nt = 0; nt < 4; ++nt)
                        mma16816(d[nt], ahi[q], bfv[q*8+nt*2], bfv[q*8+nt*2+1]);
                    #pragma unroll
                    for (int nt = 0; nt < 4; ++nt)
                        mma16816(d[nt], alo[q], bfv[q*8+nt*2], bfv[q*8+nt*2+1]);
                    #pragma unroll
                    for (int nt = 0; nt < 4; ++nt)
                        mma16816(d[nt], ahi[q], bfv[16+q*8+nt*2], bfv[16+q*8+nt*2+1]);
                }

                // epilogue: rows gq, gq+8; cols nt*8 + (lane&3)*2, +1
                u64 t0 = pk2(0.f, 0.f), t1 = pk2(0.f, 0.f);
                const int co = (lane & 3) * 2;
                #pragma unroll
                for (int nt = 0; nt < 4; ++nt) {
                    u64 bb = *reinterpret_cast<const u64*>(b2 + nt * 8 + co);
                    u64 ww = *reinterpret_cast<const u64*>(w3 + nt * 8 + co);
                    t0 = fma2(silu2p(add2(pk2(d[nt][0], d[nt][1]), bb)), ww, t0);
                    t1 = fma2(silu2p(add2(pk2(d[nt][2], d[nt][3]), bb)), ww, t1);
                }
                float s0a, s0b, s1a, s1b;
                upk2(t0, s0a, s0b);
                upk2(t1, s1a, s1b);
                float s0 = s0a + s0b, s1 = s1a + s1b;
                s0 += __shfl_xor_sync(0xFFFFFFFFu, s0, 1);
                s0 += __shfl_xor_sync(0xFFFFFFFFu, s0, 2);
                s1 += __shfl_xor_sync(0xFFFFFFFFu, s1, 1);
                s1 += __shfl_xor_sync(0xFFFFFFFFu, s1, 2);
                kk[2*T]   += silu_fp(s0 + b3);
                kk[2*T+1] += silu_fp(s1 + b3);
            }
            __syncwarp();   // before next round overwrites this warp's h rows
        }

        // ===== exp + mask + num/den over this thread's 8 epilogue keys =====
        float nc = 0.f, dc = 0.f;
        #pragma unroll
        for (int T = 0; T < 4; ++T) {
            int kap = 64 * w + 16 * T + gq;
            float fk0 = f[((size_t)b * 512 + kap) * CINc + c];
            float fk1 = f[((size_t)b * 512 + kap + 8) * CINc + c];
            float e0 = mks[2*T]   ? ex2f(LOG2E * kk[2*T])   : 0.f;
            float e1 = mks[2*T+1] ? ex2f(LOG2E * kk[2*T+1]) : 0.f;
            dc += e0 + e1;
            nc += fmaf(e0, fk0, e1 * fk1);
        }
        num[c] = nc;
        den[c] = dc;
    }

    // ---- reduce over 256 threads (quad replication x4 cancels in n/d) ----
    #pragma unroll
    for (int c = 0; c < CINc; ++c) {
        #pragma unroll
        for (int off = 16; off > 0; off >>= 1) {
            num[c] += __shfl_xor_sync(0xFFFFFFFFu, num[c], off);
            den[c] += __shfl_xor_sync(0xFFFFFFFFu, den[c], off);
        }
    }
    if (lane == 0) {
        #pragma unroll
        for (int c = 0; c < CINc; ++c) {
            sf[SRED + w * 8 + c]     = num[c];
            sf[SRED + w * 8 + 4 + c] = den[c];
        }
    }
    __syncthreads();

    if (tid < COUTc) {
        const int o = tid;
        const float mq = (mask[((size_t)b * Nc + i) * Sc + s] != 0) ? 1.0f : 0.0f;
        float acc = 0.0f;
        #pragma unroll
        for (int c = 0; c < CINc; ++c) {
            float n = 0.0f, d = 0.0f;
            #pragma unroll
            for (int ww = 0; ww < 8; ++ww) {
                n += sf[SRED + ww * 8 + c];
                d += sf[SRED + ww * 8 + 4 + c];
            }
            const float cf = (fq[c] + n / d) * mq;
            acc = fmaf(cf, sf[WOUT + o * CINc + c], acc);
        }
        out[(((size_t)b * Nc + i) * Sc + s) * COUTc + o] = acc;
    }
}

extern "C" void kernel_launch(void* const* d_in, const int* in_sizes, int n_in,
                              void* d_out, int out_size)
{
    const float* g    = (const float*)d_in[0];
    const float* f    = (const float*)d_in[1];
    const int*   mask = (const int*)d_in[2];
    const float* kyW1 = (const float*)d_in[3];
    const float* kyb1 = (const float*)d_in[4];
    const float* kyW2 = (const float*)d_in[5];
    const float* kyb2 = (const float*)d_in[6];
    const float* kyW3 = (const float*)d_in[7];
    const float* kyb3 = (const float*)d_in[8];
    const float* kgW1 = (const float*)d_in[9];
    const float* kgb1 = (const float*)d_in[10];
    const float* kgW2 = (const float*)d_in[11];
    const float* kgb2 = (const float*)d_in[12];
    const float* kgW3 = (const float*)d_in[13];
    const float* kgb3 = (const float*)d_in[14];
    const float* wout = (const float*)d_in[15];
    float* out = (float*)d_out;

    cudaFuncSetAttribute(ema_kernel, cudaFuncAttributeMaxDynamicSharedMemorySize, SMEM_BYTES);
    ema_kernel<<<Bc * Nc * Sc, 256, SMEM_BYTES>>>(g, f, mask,
                                      kyW1, kyb1, kyW2, kyb2, kyW3, kyb3,
                                      kgW1, kgb1, kgW2, kgb2, kgW3, kgb3,
                                      wout, out);
}

// round 17
// speedup vs baseline: 1.6875x; 1.0721x over previous
#include <cuda_runtime.h>
#include <cuda_bf16.h>
#include <cstdint>

#define Bc    2
#define Nc    128
#define Sc    4
#define DGc   8
#define CINc  4
#define COUTc 8
#define HIDc  32

// Dynamic smem:
// [0, 73728): h-buffer, 512 rows x 144B stride (hi bf16 [0,64), lo bf16 [64,128), pad).
//   Warp w owns rows [64w, 64w+64) exclusively -> only __syncwarp() in hot loop.
// [73728, 106496): pre-split B fragments: 8 rounds x 4KB (conflict-free LDS.128).
// floats at +106496: layer-1 weights (input-major, x0.5), biases/w3 (x0.5), wout.
#define HBUF_BYTES 73728
#define BFR 73728
#define SFOFF 106496
#define KYW1t 0        // [c][k2][o]  256
#define KGW1t 256      // [c][k8][o]  1024
#define KYB1  1280     // 128
#define KGB1  1408     // 128
#define KYB2  1536     // 128 (x0.5)
#define KGB2  1664     // 128
#define KYW3  1792     // 128 (x0.5)
#define KGW3  1920     // 128
#define KYB3  2048     // 4
#define KGB3  2052     // 4
#define WOUT  2056     // 32
#define SRED  2088     // 64
#define SF_FLOATS 2152
#define SMEM_BYTES (SFOFF + SF_FLOATS * 4)

typedef unsigned long long u64;

__device__ __forceinline__ u64 pk2(float lo, float hi) {
    u64 r; asm("mov.b64 %0, {%1, %2};" : "=l"(r) : "f"(lo), "f"(hi)); return r;
}
__device__ __forceinline__ void upk2(u64 v, float& lo, float& hi) {
    asm("mov.b64 {%0, %1}, %2;" : "=f"(lo), "=f"(hi) : "l"(v));
}
__device__ __forceinline__ u64 fma2(u64 a, u64 b, u64 c) {
    u64 d; asm("fma.rn.f32x2 %0, %1, %2, %3;" : "=l"(d) : "l"(a), "l"(b), "l"(c)); return d;
}
__device__ __forceinline__ u64 add2(u64 a, u64 b) {
    u64 d; asm("add.rn.f32x2 %0, %1, %2;" : "=l"(d) : "l"(a), "l"(b)); return d;
}
__device__ __forceinline__ float ex2f(float x) {
    float r; asm("ex2.approx.f32 %0, %1;" : "=f"(r) : "f"(x)); return r;
}
__device__ __forceinline__ float tanhf_a(float x) {
    float r; asm("tanh.approx.f32 %0, %1;" : "=f"(r) : "f"(x)); return r;
}

#define LOG2E 1.4426950408889634f

__device__ __forceinline__ u64 silu2p(u64 acc) {   // acc = x/2 -> silu(x)
    float a, b; upk2(acc, a, b);
    return fma2(acc, pk2(tanhf_a(a), tanhf_a(b)), acc);
}
__device__ __forceinline__ float silu_fp(float acc) {
    return fmaf(acc, tanhf_a(acc), acc);
}

__device__ __forceinline__ uint32_t cvt_bf2(float lo, float hi) {
    uint32_t r; asm("cvt.rn.bf16x2.f32 %0, %1, %2;" : "=r"(r) : "f"(hi), "f"(lo)); return r;
}
__device__ __forceinline__ float bfl(uint32_t h) { return __uint_as_float(h << 16); }
__device__ __forceinline__ float bfh(uint32_t h) { return __uint_as_float(h & 0xFFFF0000u); }

__device__ __forceinline__ uint32_t smem_u32(const void* p) {
    uint32_t a;
    asm("{ .reg .u64 t; cvta.to.shared.u64 t, %1; cvt.u32.u64 %0, t; }" : "=r"(a) : "l"(p));
    return a;
}

__device__ __forceinline__ void ldmx4(uint32_t* r, uint32_t addr) {
    asm volatile("ldmatrix.sync.aligned.m8n8.x4.shared.b16 {%0,%1,%2,%3}, [%4];"
                 : "=r"(r[0]), "=r"(r[1]), "=r"(r[2]), "=r"(r[3]) : "r"(addr));
}

__device__ __forceinline__ void mma16816(float* d, const uint32_t* a,
                                         uint32_t b0, uint32_t b1) {
    asm volatile("mma.sync.aligned.m16n8k16.row.col.f32.bf16.bf16.f32 "
                 "{%0,%1,%2,%3}, {%4,%5,%6,%7}, {%8,%9}, {%0,%1,%2,%3};"
                 : "+f"(d[0]), "+f"(d[1]), "+f"(d[2]), "+f"(d[3])
                 : "r"(a[0]), "r"(a[1]), "r"(a[2]), "r"(a[3]), "r"(b0), "r"(b1));
}

// cvt 4 packed pairs to bf16 hi/lo and STS as 2x 16B
__device__ __forceinline__ void cvt_sts4(const u64* hp4, char* rp_hi, char* rp_lo) {
    uint32_t h0, h1, h2, h3, l0, l1, l2, l3;
    float e0, e1;
    upk2(hp4[0], e0, e1); h0 = cvt_bf2(e0, e1); l0 = cvt_bf2(e0 - bfl(h0), e1 - bfh(h0));
    upk2(hp4[1], e0, e1); h1 = cvt_bf2(e0, e1); l1 = cvt_bf2(e0 - bfl(h1), e1 - bfh(h1));
    upk2(hp4[2], e0, e1); h2 = cvt_bf2(e0, e1); l2 = cvt_bf2(e0 - bfl(h2), e1 - bfh(h2));
    upk2(hp4[3], e0, e1); h3 = cvt_bf2(e0, e1); l3 = cvt_bf2(e0 - bfl(h3), e1 - bfh(h3));
    *reinterpret_cast<uint4*>(rp_hi) = make_uint4(h0, h1, h2, h3);
    *reinterpret_cast<uint4*>(rp_lo) = make_uint4(l0, l1, l2, l3);
}

__global__ __launch_bounds__(256, 2)
void ema_kernel(const float* __restrict__ g,
                const float* __restrict__ f,
                const int* __restrict__ mask,
                const float* __restrict__ kyW1, const float* __restrict__ kyb1,
                const float* __restrict__ kyW2, const float* __restrict__ kyb2,
                const float* __restrict__ kyW3, const float* __restrict__ kyb3,
                const float* __restrict__ kgW1, const float* __restrict__ kgb1,
                const float* __restrict__ kgW2, const float* __restrict__ kgb2,
                const float* __restrict__ kgW3, const float* __restrict__ kgb3,
                const float* __restrict__ wout,
                float* __restrict__ out)
{
    extern __shared__ __align__(16) char dsm[];
    float* sf = reinterpret_cast<float*>(dsm + SFOFF);

    const int tid  = threadIdx.x;
    const int w    = tid >> 5;
    const int lane = tid & 31;
    const int gq   = lane >> 2;

    // ---- stage layer-1 weights / biases / w3 (all x0.5, input-major) ----
    for (int idx = tid; idx < 1024; idx += 256) {
        int c = idx >> 8, o = (idx >> 3) & 31, k = idx & 7;
        sf[KGW1t + c * 256 + k * 32 + o] = 0.5f * kgW1[idx];
    }
    {
        int c = tid >> 6, o = (tid >> 1) & 31, k = tid & 1;
        sf[KYW1t + c * 64 + k * 32 + o] = 0.5f * kyW1[tid];
    }
    for (int idx = tid; idx < 128; idx += 256) {
        sf[KYB1 + idx] = 0.5f * kyb1[idx];
        sf[KGB1 + idx] = 0.5f * kgb1[idx];
        sf[KYB2 + idx] = 0.5f * kyb2[idx];
        sf[KGB2 + idx] = 0.5f * kgb2[idx];
        sf[KYW3 + idx] = 0.5f * kyW3[idx];
        sf[KGW3 + idx] = 0.5f * kgW3[idx];
    }
    if (tid < 4) { sf[KYB3 + tid] = 0.5f * kyb3[tid]; sf[KGB3 + tid] = 0.5f * kgb3[tid]; }
    if (tid < 32) sf[WOUT + tid] = wout[tid];

    // ---- stage pre-split B fragments ----
    for (int idx = tid; idx < 4096; idx += 256) {
        int r  = idx >> 9, rem2 = idx & 511, ln = rem2 >> 4, jj = rem2 & 15;
        int cc = r >> 1,  mm  = r & 1;
        int q  = jj >> 3, nt  = (jj >> 1) & 3, pr = jj & 1;
        const float* W2 = (mm ? kgW2 : kyW2) + cc * 1024;
        int o = nt * 8 + (ln >> 2);
        int k = q * 16 + pr * 8 + (ln & 3) * 2;
        float v0 = 0.5f * W2[o * 32 + k];
        float v1 = 0.5f * W2[o * 32 + k + 1];
        uint32_t hi = cvt_bf2(v0, v1);
        uint32_t lo = cvt_bf2(v0 - bfl(hi), v1 - bfh(hi));
        char* base = dsm + BFR + r * 4096 + ln * 16 + (jj & 3) * 4;
        *reinterpret_cast<uint32_t*>(base + (jj >> 2) * 512)       = hi;
        *reinterpret_cast<uint32_t*>(base + ((jj >> 2) + 4) * 512) = lo;
    }

    // ---- decode query (b, i, s) ----
    const int bid = blockIdx.x;
    const int b   = bid >> 9;
    const int rem = bid & 511;
    const int i   = rem >> 2;
    const int s   = rem & 3;

    float fq[CINc];
    {
        float4 v = *reinterpret_cast<const float4*>(f + (((size_t)b * Nc + i) * Sc + s) * CINc);
        fq[0] = v.x; fq[1] = v.y; fq[2] = v.z; fq[3] = v.w;
    }

    // ---- layer-1 keys: kapA = 64w+lane, kapB = kapA+32 ----
    const int kapA = 64 * w + lane;
    const int kapB = kapA + 32;
    const int jA = kapA >> 2;          // jB = jA + 8, same t
    const int t  = kapA & 3;

    float gA[DGc], gB[DGc];
    {
        const float* gp = g + ((((((size_t)b * Nc + i) * Nc + jA) * Sc + s) * Sc) + t) * DGc;
        float4 g0 = *reinterpret_cast<const float4*>(gp);
        float4 g1 = *reinterpret_cast<const float4*>(gp + 4);
        gA[0]=g0.x; gA[1]=g0.y; gA[2]=g0.z; gA[3]=g0.w;
        gA[4]=g1.x; gA[5]=g1.y; gA[6]=g1.z; gA[7]=g1.w;
        const float* gp2 = gp + (size_t)8 * Sc * Sc * DGc;   // j + 8
        float4 h0 = *reinterpret_cast<const float4*>(gp2);
        float4 h1 = *reinterpret_cast<const float4*>(gp2 + 4);
        gB[0]=h0.x; gB[1]=h0.y; gB[2]=h0.z; gB[3]=h0.w;
        gB[4]=h1.x; gB[5]=h1.y; gB[6]=h1.z; gB[7]=h1.w;
    }
    float fkA[CINc], fkB[CINc];
    {
        float4 v = *reinterpret_cast<const float4*>(f + ((size_t)b * 512 + kapA) * CINc);
        fkA[0]=v.x; fkA[1]=v.y; fkA[2]=v.z; fkA[3]=v.w;
        float4 x = *reinterpret_cast<const float4*>(f + ((size_t)b * 512 + kapB) * CINc);
        fkB[0]=x.x; fkB[1]=x.y; fkB[2]=x.z; fkB[3]=x.w;
    }

    // ---- epilogue keys: kappa = 64w + 16T + gq (+8) ----
    int mks[8];
    #pragma unroll
    for (int T = 0; T < 4; ++T) {
        int kap = 64 * w + 16 * T + gq;
        mks[2*T]   = mask[(size_t)b * 512 + kap];
        mks[2*T+1] = mask[(size_t)b * 512 + kap + 8];
    }

    __syncthreads();   // staging complete; hot loop is warp-local

    const uint32_t hb = smem_u32(dsm);
    float num[CINc], den[CINc];

    #pragma unroll 1
    for (int c = 0; c < CINc; ++c) {
        float kk[8];
        #pragma unroll
        for (int q = 0; q < 8; ++q) kk[q] = 0.f;

        #pragma unroll     // m=1 layer-1 overlaps m=0 MMA/epilogue
        for (int m = 0; m < 2; ++m) {
            // ===== layer 1 in two o-halves: 16 hp regs live, fused cvt+STS =====
            #pragma unroll
            for (int half = 0; half < 2; ++half) {
                u64 hpA[8], hpB[8];
                if (m == 0) {
                    const float* w1 = sf + KYW1t + c * 64 + half * 16;
                    const float* b1 = sf + KYB1 + c * 32 + half * 16;
                    const u64 fqd  = pk2(fq[c], fq[c]);
                    const u64 fkAd = pk2(fkA[c], fkA[c]);
                    const u64 fkBd = pk2(fkB[c], fkB[c]);
                    #pragma unroll
                    for (int q = 0; q < 4; ++q) {
                        ulonglong2 w0 = *reinterpret_cast<const ulonglong2*>(w1 + 4*q);
                        ulonglong2 wq = *reinterpret_cast<const ulonglong2*>(w1 + 32 + 4*q);
                        ulonglong2 bv = *reinterpret_cast<const ulonglong2*>(b1 + 4*q);
                        u64 t0 = fma2(fqd, wq.x, bv.x);
                        u64 t1 = fma2(fqd, wq.y, bv.y);
                        hpA[2*q]   = fma2(fkAd, w0.x, t0);
                        hpA[2*q+1] = fma2(fkAd, w0.y, t1);
                        hpB[2*q]   = fma2(fkBd, w0.x, t0);
                        hpB[2*q+1] = fma2(fkBd, w0.y, t1);
                    }
                } else {
                    const float* w1 = sf + KGW1t + c * 256 + half * 16;
                    const float* b1 = sf + KGB1 + c * 32 + half * 16;
                    #pragma unroll
                    for (int q = 0; q < 4; ++q) {
                        ulonglong2 bv = *reinterpret_cast<const ulonglong2*>(b1 + 4*q);
                        hpA[2*q] = bv.x; hpA[2*q+1] = bv.y;
                        hpB[2*q] = bv.x; hpB[2*q+1] = bv.y;
                    }
                    #pragma unroll
                    for (int k = 0; k < DGc; ++k) {
                        const u64 gad = pk2(gA[k], gA[k]);
                        const u64 gbd = pk2(gB[k], gB[k]);
                        const float* wk = w1 + k * 32;
                        #pragma unroll
                        for (int q = 0; q < 4; ++q) {
                            ulonglong2 wv = *reinterpret_cast<const ulonglong2*>(wk + 4*q);
                            hpA[2*q]   = fma2(gad, wv.x, hpA[2*q]);
                            hpA[2*q+1] = fma2(gad, wv.y, hpA[2*q+1]);
                            hpB[2*q]   = fma2(gbd, wv.x, hpB[2*q]);
                            hpB[2*q+1] = fma2(gbd, wv.y, hpB[2*q+1]);
                        }
                    }
                }
                #pragma unroll
                for (int p = 0; p < 8; ++p) { hpA[p] = silu2p(hpA[p]); hpB[p] = silu2p(hpB[p]); }

                // fused cvt + STS (rows kapA, kapB; byte offset half*32)
                char* rpA = dsm + kapA * 144 + half * 32;
                char* rpB = dsm + kapB * 144 + half * 32;
                cvt_sts4(hpA,     rpA,      rpA + 64);
                cvt_sts4(hpA + 4, rpA + 16, rpA + 80);
                cvt_sts4(hpB,     rpB,      rpB + 64);
                cvt_sts4(hpB + 4, rpB + 16, rpB + 80);
            }

            // ===== B fragments (LDS latency drains under syncwarp) =====
            uint32_t bfv[32];
            {
                const char* bp = dsm + BFR + (c * 2 + m) * 4096 + lane * 16;
                #pragma unroll
                for (int ch2 = 0; ch2 < 8; ++ch2) {
                    uint4 v = *reinterpret_cast<const uint4*>(bp + ch2 * 512);
                    bfv[ch2*4+0] = v.x; bfv[ch2*4+1] = v.y;
                    bfv[ch2*4+2] = v.z; bfv[ch2*4+3] = v.w;
                }
            }
            __syncwarp();

            // ===== per-tile: ldmatrix A, 24 MMAs, epilogue =====
            const float* b2 = sf + (m ? KGB2 : KYB2) + c * HIDc;
            const float* w3 = sf + (m ? KGW3 : KYW3) + c * HIDc;
            const float  b3 = sf[(m ? KGB3 : KYB3) + c];
            const uint32_t lmbase = hb
                + (uint32_t)(64 * w + (lane & 7) + ((lane >> 3) & 1) * 8) * 144
                + ((lane >> 4) & 1) * 16;

            #pragma unroll 2   // tile t+1 ldmatrix/MMA overlaps tile t epilogue
            for (int T = 0; T < 4; ++T) {
                uint32_t ahi[2][4], alo[2][4];
                const uint32_t ab = lmbase + (uint32_t)(16 * T) * 144;
                ldmx4(ahi[0], ab);
                ldmx4(ahi[1], ab + 32);
                ldmx4(alo[0], ab + 64);
                ldmx4(alo[1], ab + 96);

                float d[4][4];
                #pragma unroll
                for (int nt = 0; nt < 4; ++nt)
                    d[nt][0] = d[nt][1] = d[nt][2] = d[nt][3] = 0.f;

                #pragma unroll
                for (int q = 0; q < 2; ++q) {
                    #pragma unroll
                    for (int nt = 0; nt < 4; ++nt)
                        mma16816(d[nt], ahi[q], bfv[q*8+nt*2], bfv[q*8+nt*2+1]);
                    #pragma unroll
                    for (int nt = 0; nt < 4; ++nt)
                        mma16816(d[nt], alo[q], bfv[q*8+nt*2], bfv[q*8+nt*2+1]);
                    #pragma unroll
                    for (int nt = 0; nt < 4; ++nt)
                        mma16816(d[nt], ahi[q], bfv[16+q*8+nt*2], bfv[16+q*8+nt*2+1]);
                }

                // epilogue: rows gq, gq+8; cols nt*8 + (lane&3)*2, +1
                u64 t0 = pk2(0.f, 0.f), t1 = pk2(0.f, 0.f);
                const int co = (lane & 3) * 2;
                #pragma unroll
                for (int nt = 0; nt < 4; ++nt) {
                    u64 bb = *reinterpret_cast<const u64*>(b2 + nt * 8 + co);
                    u64 ww = *reinterpret_cast<const u64*>(w3 + nt * 8 + co);
                    t0 = fma2(silu2p(add2(pk2(d[nt][0], d[nt][1]), bb)), ww, t0);
                    t1 = fma2(silu2p(add2(pk2(d[nt][2], d[nt][3]), bb)), ww, t1);
                }
                float s0a, s0b, s1a, s1b;
                upk2(t0, s0a, s0b);
                upk2(t1, s1a, s1b);
                float s0 = s0a + s0b, s1 = s1a + s1b;
                s0 += __shfl_xor_sync(0xFFFFFFFFu, s0, 1);
                s0 += __shfl_xor_sync(0xFFFFFFFFu, s0, 2);
                s1 += __shfl_xor_sync(0xFFFFFFFFu, s1, 1);
                s1 += __shfl_xor_sync(0xFFFFFFFFu, s1, 2);
                kk[2*T]   += silu_fp(s0 + b3);
                kk[2*T+1] += silu_fp(s1 + b3);
            }
            __syncwarp();   // before next round overwrites this warp's h rows
        }

        // ===== exp + mask + num/den over this thread's 8 epilogue keys =====
        float nc = 0.f, dc = 0.f;
        #pragma unroll
        for (int T = 0; T < 4; ++T) {
            int kap = 64 * w + 16 * T + gq;
            float fk0 = f[((size_t)b * 512 + kap) * CINc + c];
            float fk1 = f[((size_t)b * 512 + kap + 8) * CINc + c];
            float e0 = mks[2*T]   ? ex2f(LOG2E * kk[2*T])   : 0.f;
            float e1 = mks[2*T+1] ? ex2f(LOG2E * kk[2*T+1]) : 0.f;
            dc += e0 + e1;
            nc += fmaf(e0, fk0, e1 * fk1);
        }
        num[c] = nc;
        den[c] = dc;
    }

    // ---- reduce over 256 threads (quad replication x4 cancels in n/d) ----
    #pragma unroll
    for (int c = 0; c < CINc; ++c) {
        #pragma unroll
        for (int off = 16; off > 0; off >>= 1) {
            num[c] += __shfl_xor_sync(0xFFFFFFFFu, num[c], off);
            den[c] += __shfl_xor_sync(0xFFFFFFFFu, den[c], off);
        }
    }
    if (lane == 0) {
        #pragma unroll
        for (int c = 0; c < CINc; ++c) {
            sf[SRED + w * 8 + c]     = num[c];
            sf[SRED + w * 8 + 4 + c] = den[c];
        }
    }
    __syncthreads();

    if (tid < COUTc) {
        const int o = tid;
        const float mq = (mask[((size_t)b * Nc + i) * Sc + s] != 0) ? 1.0f : 0.0f;
        float acc = 0.0f;
        #pragma unroll
        for (int c = 0; c < CINc; ++c) {
            float n = 0.0f, d = 0.0f;
            #pragma unroll
            for (int ww = 0; ww < 8; ++ww) {
                n += sf[SRED + ww * 8 + c];
                d += sf[SRED + ww * 8 + 4 + c];
            }
            const float cf = (fq[c] + n / d) * mq;
            acc = fmaf(cf, sf[WOUT + o * CINc + c], acc);
        }
        out[(((size_t)b * Nc + i) * Sc + s) * COUTc + o] = acc;
    }
}

extern "C" void kernel_launch(void* const* d_in, const int* in_sizes, int n_in,
                              void* d_out, int out_size)
{
    const float* g    = (const float*)d_in[0];
    const float* f    = (const float*)d_in[1];
    const int*   mask = (const int*)d_in[2];
    const float* kyW1 = (const float*)d_in[3];
    const float* kyb1 = (const float*)d_in[4];
    const float* kyW2 = (const float*)d_in[5];
    const float* kyb2 = (const float*)d_in[6];
    const float* kyW3 = (const float*)d_in[7];
    const float* kyb3 = (const float*)d_in[8];
    const float* kgW1 = (const float*)d_in[9];
    const float* kgb1 = (const float*)d_in[10];
    const float* kgW2 = (const float*)d_in[11];
    const float* kgb2 = (const float*)d_in[12];
    const float* kgW3 = (const float*)d_in[13];
    const float* kgb3 = (const float*)d_in[14];
    const float* wout = (const float*)d_in[15];
    float* out = (float*)d_out;

    cudaFuncSetAttribute(ema_kernel, cudaFuncAttributeMaxDynamicSharedMemorySize, SMEM_BYTES);
    ema_kernel<<<Bc * Nc * Sc, 256, SMEM_BYTES>>>(g, f, mask,
                                      kyW1, kyb1, kyW2, kyb2, kyW3, kyb3,
                                      kgW1, kgb1, kgW2, kgb2, kgW3, kgb3,
                                      wout, out);
}